// round 3
// baseline (speedup 1.0000x reference)
#include <cuda_runtime.h>
#include <math.h>

#define N_IN  8000
#define NS    4000
#define D     64
#define H     128
#define EK    15
#define KNN   16
#define NPAIR 120
#define MAXD  256
#define NBM   ((NS + 31) / 32)

// ---------------- scratch (no allocations allowed) ----------------
__device__ float g_prob[N_IN];
__device__ int   g_sel[NS];
__device__ float g_sx[NS * D];
__device__ float g_sp[NS * 3];
__device__ float g_sq[NS];
__device__ int   g_nbr[NS * EK];
__device__ float g_adj[(size_t)NS * NS];     // 64 MB dense adjacency
__device__ int   g_deg[NS];
__device__ int   g_scol[NS * MAXD];
__device__ float g_sval[NS * MAXD];
__device__ float g_norm[NS];
__device__ int   g_knn[NS * KNN];
__device__ float g_p[NS * H];

// fast sigmoid for continuous-only outputs
__device__ __forceinline__ float sigmoid_fast(float v) { return 1.0f / (1.0f + expf(-v)); }
// near-correctly-rounded fp32 sigmoid 1/(1+exp(-x)) — matches libm expf bits
__device__ __forceinline__ float sigmoid_exact(float v) {
    float e = (float)exp(-(double)v);                 // correctly-rounded fp32 exp
    return __fdiv_rn(1.0f, __fadd_rn(1.0f, e));
}

// ---------------- 1. probs = sigmoid(relu(x@W1 + b1) @ w2), Eigen bit-model ----------------
// Every dot: single fma chain, ascending k, acc starts at 0; bias added AFTER.
__global__ void k_logits(const float* __restrict__ x, const float* __restrict__ W1,
                         const float* __restrict__ b1, const float* __restrict__ w2) {
    __shared__ float sW[D * H];
    __shared__ float sw2[H];
    __shared__ float sb1[H];
    __shared__ float sh[8][H];          // per-warp h row
    int tid = threadIdx.x;
    for (int t = tid; t < D * H; t += blockDim.x) sW[t] = W1[t];
    if (tid < H) { sw2[tid] = w2[tid]; sb1[tid] = b1[tid]; }
    __syncthreads();
    int warp = (blockIdx.x * blockDim.x + tid) >> 5;
    int wloc = (tid >> 5);
    int lane = tid & 31;
    if (warp >= N_IN) return;
    const float* xr = x + warp * D;
    float acc[4] = {0.f, 0.f, 0.f, 0.f};
#pragma unroll 8
    for (int d = 0; d < D; d++) {
        float xv = xr[d];
#pragma unroll
        for (int q = 0; q < 4; q++) acc[q] = fmaf(xv, sW[d * H + lane + q * 32], acc[q]);
    }
#pragma unroll
    for (int q = 0; q < 4; q++) {
        int j = lane + q * 32;
        sh[wloc][j] = fmaxf(__fadd_rn(acc[q], sb1[j]), 0.0f);   // (dot)+b1, relu
    }
    __syncwarp();
    if (lane == 0) {
        float logit = 0.0f;
#pragma unroll 8
        for (int j = 0; j < H; j++) logit = fmaf(sh[wloc][j], sw2[j], logit);  // ascending chain
        g_prob[warp] = sigmoid_exact(logit);
    }
}

// ---------------- 2. full descending sort on (prob32, index) ----------------
__global__ void k_sort() {
    extern __shared__ unsigned long long s[];   // 8192 keys = 64 KB
    int tid = threadIdx.x;                       // 1024 threads
    for (int i = tid; i < 8192; i += 1024) {
        unsigned long long key = 0ull;
        if (i < N_IN) {
            unsigned int b = __float_as_uint(g_prob[i]);
            b = (b & 0x80000000u) ? ~b : (b | 0x80000000u);   // sortable transform
            key = ((unsigned long long)b << 32) | (unsigned long long)(8191 - i);
        }
        s[i] = key;
    }
    __syncthreads();
    for (int k = 2; k <= 8192; k <<= 1) {
        for (int j = k >> 1; j > 0; j >>= 1) {
            for (int i = tid; i < 8192; i += 1024) {
                int ixj = i ^ j;
                if (ixj > i) {
                    bool desc = ((i & k) == 0);
                    unsigned long long a = s[i], b = s[ixj];
                    if (desc ? (a < b) : (a > b)) { s[i] = b; s[ixj] = a; }
                }
            }
            __syncthreads();
        }
    }
    for (int r = tid; r < NS; r += 1024)
        g_sel[r] = 8191 - (int)(s[r] & 0xFFFFFFFFull);
}

// ---------------- 3. gather sx/sp, precompute |sp|^2 ----------------
__global__ void k_gather(const float* __restrict__ x, const float* __restrict__ pos) {
    int t = blockIdx.x * blockDim.x + threadIdx.x;
    if (t < NS * D) {
        int r = t >> 6, d = t & 63;
        g_sx[t] = x[g_sel[r] * D + d];
    }
    if (t < NS * 3) {
        int r = t / 3, c = t % 3;
        g_sp[t] = pos[g_sel[r] * 3 + c];
    }
    if (t < NS) {
        int sI = g_sel[t];
        float a = pos[sI * 3], b = pos[sI * 3 + 1], c = pos[sI * 3 + 2];
        g_sq[t] = __fadd_rn(__fadd_rn(__fmul_rn(a, a), __fmul_rn(b, b)), __fmul_rn(c, c));
    }
}

// ---------------- 4. spatial 15-NN (ascending d2, index tie-break) ----------------
__global__ void k_knn_space() {
    __shared__ float4 tile[256];
    int i = blockIdx.x * 128 + threadIdx.x;
    float xi = 0, yi = 0, zi = 0, sqi = 0;
    if (i < NS) { xi = g_sp[i * 3]; yi = g_sp[i * 3 + 1]; zi = g_sp[i * 3 + 2]; sqi = g_sq[i]; }
    float bd[EK]; int bi[EK];
#pragma unroll
    for (int t = 0; t < EK; t++) { bd[t] = INFINITY; bi[t] = 0x7FFFFFFF; }
    for (int base = 0; base < NS; base += 256) {
        __syncthreads();
        for (int t = threadIdx.x; t < 256; t += 128) {
            int j = base + t;
            if (j < NS) tile[t] = make_float4(g_sp[j * 3], g_sp[j * 3 + 1], g_sp[j * 3 + 2], g_sq[j]);
        }
        __syncthreads();
        if (i < NS) {
            int lim = min(256, NS - base);
            for (int t = 0; t < lim; t++) {
                int j = base + t;
                if (j == i) continue;
                float4 p = tile[t];
                float dot = fmaf(zi, p.z, fmaf(yi, p.y, __fmul_rn(xi, p.x)));  // chain from 0
                float d2 = __fsub_rn(__fadd_rn(sqi, p.w), __fmul_rn(2.0f, dot)); // 2*dot exact
                if (d2 < bd[EK - 1]) {              // strict < : earlier index wins ties
                    bd[EK - 1] = d2; bi[EK - 1] = j;
#pragma unroll
                    for (int t2 = EK - 1; t2 > 0; t2--) {
                        if (bd[t2] < bd[t2 - 1]) {
                            float a = bd[t2]; bd[t2] = bd[t2 - 1]; bd[t2 - 1] = a;
                            int   b = bi[t2]; bi[t2] = bi[t2 - 1]; bi[t2 - 1] = b;
                        }
                    }
                }
            }
        }
    }
    if (i < NS)
#pragma unroll
        for (int t = 0; t < EK; t++) g_nbr[i * EK + t] = bi[t];
}

// ---------------- 5. zero dense adj ----------------
__global__ void k_zero() {
    size_t t = (size_t)blockIdx.x * blockDim.x + threadIdx.x;
    float4* p = (float4*)g_adj;
    size_t n = (size_t)NS * NS / 4;
    for (size_t q = t; q < n; q += (size_t)gridDim.x * blockDim.x)
        p[q] = make_float4(0.f, 0.f, 0.f, 0.f);
}

// ---------------- 6. edge probs -> symmetric adjacency (exact sigmoid bits) ----------------
__global__ void k_edges(const float* __restrict__ w_e) {
    __shared__ float swe[D];
    if (threadIdx.x < D) swe[threadIdx.x] = w_e[threadIdx.x];
    __syncthreads();
    int e = blockIdx.x * blockDim.x + threadIdx.x;
    if (e >= NS * EK) return;
    int i = e / EK;
    int j = g_nbr[e];
    const float* a = g_sx + i * D;
    const float* b = g_sx + j * D;
    float acc = 0.0f;
#pragma unroll 8
    for (int d = 0; d < D; d++)
        acc = fmaf(__fmul_rn(a[d], b[d]), swe[d], acc);   // bitwise symmetric in (i,j)
    float ep = sigmoid_exact(acc);
    g_adj[(size_t)i * NS + j] = ep;   // value-identical race with reverse edge: benign
    g_adj[(size_t)j * NS + i] = ep;
}

// ---------------- 7. CSR support per row (ascending j), 1 warp/row ----------------
__global__ void k_supp() {
    int warp = (blockIdx.x * blockDim.x + threadIdx.x) >> 5;
    int lane = threadIdx.x & 31;
    if (warp >= NS) return;
    const float* row = g_adj + (size_t)warp * NS;
    int cnt = 0;
    for (int base = 0; base < NS; base += 32) {
        float v = row[base + lane];
        unsigned m = __ballot_sync(0xffffffffu, v != 0.0f);
        if (v != 0.0f) {
            int pos = cnt + __popc(m & ((1u << lane) - 1u));
            if (pos < MAXD) { g_scol[warp * MAXD + pos] = base + lane; g_sval[warp * MAXD + pos] = v; }
        }
        cnt += __popc(m);
    }
    if (lane == 0) g_deg[warp] = min(cnt, MAXD);
}

// ---------------- 8. row norms (ascending sequential; zeros exact no-ops) ----------------
__global__ void k_norm() {
    int i = blockIdx.x * blockDim.x + threadIdx.x;
    if (i >= NS) return;
    int dg = g_deg[i];
    const float* v = g_sval + i * MAXD;
    float s = 0.0f;
    for (int t = 0; t < dg; t++) s = __fadd_rn(s, __fmul_rn(v[t], v[t]));
    g_norm[i] = s;
}

// ---------------- 9. sparse fd2 + top-16 per row (1 block/row) ----------------
__global__ void k_fd2() {
    __shared__ unsigned int sbm[NBM];
    __shared__ int   scol[MAXD];
    __shared__ float sval[MAXD];
    __shared__ float rbest[128];
    __shared__ int   rbj[128];
    int i = blockIdx.x;
    int tid = threadIdx.x;
    int dg = g_deg[i];
    for (int t = tid; t < NBM; t += 128) sbm[t] = 0u;
    for (int t = tid; t < dg; t += 128) { scol[t] = g_scol[i * MAXD + t]; sval[t] = g_sval[i * MAXD + t]; }
    __syncthreads();
    // phase A: mark 2-hop candidates (adj symmetric -> col support == row support)
    int wrp = tid >> 5, ln = tid & 31;
    for (int u = wrp; u < dg; u += 4) {
        int k = scol[u];
        int dk = g_deg[k];
        const int* ck = g_scol + k * MAXD;
        for (int t = ln; t < dk; t += 32) {
            int j = ck[t];
            atomicOr(&sbm[j >> 5], 1u << (j & 31));
        }
    }
    __syncthreads();
    // phase B: fd2 for all j, exact sparse dot only where support overlaps
    float ni = g_norm[i];
    float bd[KNN]; int bj[KNN];
#pragma unroll
    for (int t = 0; t < KNN; t++) { bd[t] = INFINITY; bj[t] = 0x7FFFFFFF; }
    for (int j = tid; j < NS; j += 128) {
        if (j == i) continue;
        float dot = 0.0f;
        if ((sbm[j >> 5] >> (j & 31)) & 1u) {
            const float* rowj = g_adj + (size_t)j * NS;
            for (int t = 0; t < dg; t++)
                dot = fmaf(sval[t], rowj[scol[t]], dot);   // ascending k, zeros exact no-ops
        }
        float fd2 = __fsub_rn(__fadd_rn(ni, g_norm[j]), __fmul_rn(2.0f, dot));
        if (fd2 < bd[KNN - 1]) {
            bd[KNN - 1] = fd2; bj[KNN - 1] = j;
#pragma unroll
            for (int t = KNN - 1; t > 0; t--) {
                if (bd[t] < bd[t - 1]) {
                    float a = bd[t]; bd[t] = bd[t - 1]; bd[t - 1] = a;
                    int   b = bj[t]; bj[t] = bj[t - 1]; bj[t - 1] = b;
                }
            }
        }
    }
    __syncthreads();
    // phase C: 16x block argmin with (fd2, j) lexicographic tie-break
    for (int t = 0; t < KNN; t++) {
        rbest[tid] = bd[0]; rbj[tid] = bj[0];
        __syncthreads();
        for (int s = 64; s > 0; s >>= 1) {
            if (tid < s) {
                float fb = rbest[tid + s]; int jb = rbj[tid + s];
                if (fb < rbest[tid] || (fb == rbest[tid] && jb < rbj[tid])) { rbest[tid] = fb; rbj[tid] = jb; }
            }
            __syncthreads();
        }
        float wf = rbest[0]; int wj = rbj[0];
        if (tid == 0) g_knn[i * KNN + t] = wj;
        if (bj[0] == wj && bd[0] == wf) {          // unique owner pops its head
#pragma unroll
            for (int q = 0; q < KNN - 1; q++) { bd[q] = bd[q + 1]; bj[q] = bj[q + 1]; }
            bd[KNN - 1] = INFINITY; bj[KNN - 1] = 0x7FFFFFFF;
        }
        __syncthreads();
    }
}

// ---------------- 10. per-vertex MLP projection p_v = [sx_v, sp_v] @ Wf1 ----------------
__global__ void k_pfeat(const float* __restrict__ Wf1) {
    __shared__ float sW[(D + 3) * H];   // 34.3 KB
    int tid = threadIdx.x;
    for (int t = tid; t < (D + 3) * H; t += blockDim.x) sW[t] = Wf1[t];
    __syncthreads();
    int warp = (blockIdx.x * blockDim.x + tid) >> 5;
    int lane = tid & 31;
    if (warp >= NS) return;
    float acc[4] = {0.f, 0.f, 0.f, 0.f};
#pragma unroll 8
    for (int d = 0; d < D; d++) {
        float xv = g_sx[warp * D + d];
#pragma unroll
        for (int q = 0; q < 4; q++) acc[q] = fmaf(xv, sW[d * H + lane + q * 32], acc[q]);
    }
#pragma unroll
    for (int c = 0; c < 3; c++) {
        float pv = g_sp[warp * 3 + c];
#pragma unroll
        for (int q = 0; q < 4; q++) acc[q] = fmaf(pv, sW[(D + c) * H + lane + q * 32], acc[q]);
    }
#pragma unroll
    for (int q = 0; q < 4; q++) g_p[warp * H + lane + q * 32] = acc[q];
}

// ---------------- 11. triangles: fprob/tprob (1 block/row, thread/pair) ----------------
__global__ void k_tri(const float* __restrict__ bf1, const float* __restrict__ wf2,
                      float* __restrict__ out) {
    __shared__ float spn[KNN * 132];   // padded rows: no bank conflicts
    __shared__ float spi[H];
    __shared__ float sb[H];
    __shared__ float sw[H];
    __shared__ int   sknn[KNN];
    __shared__ float sain[KNN];
    int i = blockIdx.x, tid = threadIdx.x;
    if (tid < KNN) sknn[tid] = g_knn[i * KNN + tid];
    if (tid < H) { spi[tid] = g_p[i * H + tid]; sb[tid] = bf1[tid]; sw[tid] = wf2[tid]; }
    __syncthreads();
    for (int t = tid; t < KNN * H; t += 128) {
        int r = t >> 7, h = t & 127;
        spn[r * 132 + h] = g_p[sknn[r] * H + h];
    }
    if (tid < KNN) sain[tid] = g_adj[(size_t)i * NS + sknn[tid]];
    __syncthreads();
    if (tid < NPAIR) {
        int rem = tid, jj = 0;
        while (rem >= EK - jj) { rem -= EK - jj; jj++; }   // triu_indices(16,1) order
        int ll = jj + 1 + rem;
        int n1 = sknn[jj], n2 = sknn[ll];
        float a12 = g_adj[(size_t)n1 * NS + n2];
        const float* p1 = spn + jj * 132;
        const float* p2 = spn + ll * 132;
        float acc = 0.0f;
#pragma unroll 8
        for (int h = 0; h < H; h++) {
            float pre = __fadd_rn(__fdiv_rn(__fadd_rn(__fadd_rn(spi[h], p1[h]), p2[h]), 3.0f),
                                  sb[h]);
            acc = fmaf(fmaxf(pre, 0.0f), sw[h], acc);
        }
        float valid = (a12 > 0.0f) ? 1.0f : 0.0f;
        float fp = sigmoid_fast(acc) * valid;     // continuous output: fast path OK
        float prod = __fmul_rn(__fmul_rn(sain[jj], sain[ll]), a12);
        float tp = (a12 > 0.0f) ? cbrtf(fmaxf(prod, 1e-9f)) : 0.0f;
        out[(size_t)i * NPAIR + tid]                    = fp;
        out[(size_t)NS * NPAIR + (size_t)i * NPAIR + tid] = tp;
    }
}

// ---------------- launch ----------------
extern "C" void kernel_launch(void* const* d_in, const int* in_sizes, int n_in,
                              void* d_out, int out_size) {
    const float* x   = (const float*)d_in[0];
    const float* pos = (const float*)d_in[1];
    const float* W1  = (const float*)d_in[2];
    const float* b1  = (const float*)d_in[3];
    const float* w2  = (const float*)d_in[4];
    const float* w_e = (const float*)d_in[5];
    const float* Wf1 = (const float*)d_in[6];
    const float* bf1 = (const float*)d_in[7];
    const float* wf2 = (const float*)d_in[8];
    float* out = (float*)d_out;

    cudaFuncSetAttribute(k_sort, cudaFuncAttributeMaxDynamicSharedMemorySize, 8192 * 8);

    k_zero<<<512, 256>>>();
    k_logits<<<(N_IN * 32 + 255) / 256, 256>>>(x, W1, b1, w2);
    k_sort<<<1, 1024, 8192 * 8>>>();
    k_gather<<<(NS * D + 255) / 256, 256>>>(x, pos);
    k_knn_space<<<(NS + 127) / 128, 128>>>();
    k_edges<<<(NS * EK + 255) / 256, 256>>>(w_e);
    k_supp<<<(NS * 32 + 255) / 256, 256>>>();
    k_norm<<<(NS + 255) / 256, 256>>>();
    k_fd2<<<NS, 128>>>();
    k_pfeat<<<(NS * 32 + 255) / 256, 256>>>(Wf1);
    k_tri<<<NS, 128>>>(bf1, wf2, out);
}

// round 4
// speedup vs baseline: 2.1175x; 2.1175x over previous
#include <cuda_runtime.h>
#include <math.h>

#define N_IN  8000
#define NSORT 8192
#define NS    4000
#define D     64
#define H     128
#define EK    15
#define KNN   16
#define NPAIR 120
#define MAXD  256

// ---------------- scratch (no allocations allowed) ----------------
__device__ float g_prob[N_IN];
__device__ unsigned long long g_keys[NSORT];
__device__ float g_sx[NS * D];
__device__ float g_sp[NS * 3];
__device__ float4 g_sp4[NS];
__device__ int   g_nbr[NS * EK];
__device__ float g_adj[(size_t)NS * NS];     // 64 MB dense adjacency
__device__ int   g_deg[NS];
__device__ int   g_scol[NS * MAXD];
__device__ float g_sval[NS * MAXD];
__device__ float g_norm[NS];
__device__ int   g_knn[NS * KNN];
__device__ float g_p[NS * H];

__device__ __forceinline__ float sigmoid_fast(float v) { return 1.0f / (1.0f + expf(-v)); }
// near-correctly-rounded fp32 sigmoid — matches libm expf bits
__device__ __forceinline__ float sigmoid_exact(float v) {
    float e = (float)exp(-(double)v);
    return __fdiv_rn(1.0f, __fadd_rn(1.0f, e));
}
__device__ __forceinline__ unsigned int f32_sortable(float f) {
    unsigned int b = __float_as_uint(f);
    return (b & 0x80000000u) ? ~b : (b | 0x80000000u);
}
__device__ __forceinline__ int sel_of(int r) {
    return 8191 - (int)(g_keys[r] & 0xFFFFFFFFull);
}

// ---------------- 1. probs = sigmoid(relu(x@W1 + b1) @ w2), Eigen bit-model ----------------
__global__ void k_logits(const float* __restrict__ x, const float* __restrict__ W1,
                         const float* __restrict__ b1, const float* __restrict__ w2) {
    __shared__ float sW[D * H];
    __shared__ float sw2[H];
    __shared__ float sb1[H];
    __shared__ float sh[8][H];
    int tid = threadIdx.x;
    for (int t = tid; t < D * H; t += blockDim.x) sW[t] = W1[t];
    if (tid < H) { sw2[tid] = w2[tid]; sb1[tid] = b1[tid]; }
    __syncthreads();
    int warp = (blockIdx.x * blockDim.x + tid) >> 5;
    int wloc = (tid >> 5);
    int lane = tid & 31;
    if (warp >= N_IN) return;
    const float* xr = x + warp * D;
    float acc[4] = {0.f, 0.f, 0.f, 0.f};
#pragma unroll 8
    for (int d = 0; d < D; d++) {
        float xv = xr[d];
#pragma unroll
        for (int q = 0; q < 4; q++) acc[q] = fmaf(xv, sW[d * H + lane + q * 32], acc[q]);
    }
#pragma unroll
    for (int q = 0; q < 4; q++) {
        int j = lane + q * 32;
        sh[wloc][j] = fmaxf(__fadd_rn(acc[q], sb1[j]), 0.0f);
    }
    __syncwarp();
    if (lane == 0) {
        float logit = 0.0f;
#pragma unroll 8
        for (int j = 0; j < H; j++) logit = fmaf(sh[wloc][j], sw2[j], logit);
        g_prob[warp] = sigmoid_exact(logit);
    }
}

// ---------------- 2. build sortable keys (prob desc, index-asc tiebreak) ----------------
__global__ void k_keys() {
    int i = blockIdx.x * blockDim.x + threadIdx.x;
    if (i >= NSORT) return;
    unsigned long long key = 0ull;
    if (i < N_IN)
        key = ((unsigned long long)f32_sortable(g_prob[i]) << 32)
            | (unsigned long long)(8191 - i);
    g_keys[i] = key;
}

// Multi-block bitonic: identical network, redistributed. Final order descending.
__device__ __forceinline__ void bitonic_cmp(unsigned long long* s, int gl, int gp, int l, int p, int k) {
    bool desc = ((gl & k) == 0);
    unsigned long long a = s[l], b = s[p];
    if (desc ? (a < b) : (a > b)) { s[l] = b; s[p] = a; }
}
__global__ void k_sortL1() {   // stages k=2..2048 inside each 2048-chunk
    __shared__ unsigned long long s[2048];
    int base = blockIdx.x * 2048;
    int tid = threadIdx.x;   // 1024
    for (int t = tid; t < 2048; t += 1024) s[t] = g_keys[base + t];
    __syncthreads();
    for (int k = 2; k <= 2048; k <<= 1)
        for (int j = k >> 1; j > 0; j >>= 1) {
            for (int l = tid; l < 2048; l += 1024) {
                int p = l ^ j;
                if (p > l) bitonic_cmp(s, base + l, base + p, l, p, k);
            }
            __syncthreads();
        }
    for (int t = tid; t < 2048; t += 1024) g_keys[base + t] = s[t];
}
__global__ void k_sortG(int k, int j) {   // one global compare pass
    int t = blockIdx.x * blockDim.x + threadIdx.x;
    if (t >= NSORT) return;
    int p = t ^ j;
    if (p > t) {
        bool desc = ((t & k) == 0);
        unsigned long long a = g_keys[t], b = g_keys[p];
        if (desc ? (a < b) : (a > b)) { g_keys[t] = b; g_keys[p] = a; }
    }
}
__global__ void k_sortT(int k) {   // tail j=1024..1 inside each 2048-chunk
    __shared__ unsigned long long s[2048];
    int base = blockIdx.x * 2048;
    int tid = threadIdx.x;
    for (int t = tid; t < 2048; t += 1024) s[t] = g_keys[base + t];
    __syncthreads();
    for (int j = 1024; j > 0; j >>= 1) {
        for (int l = tid; l < 2048; l += 1024) {
            int p = l ^ j;
            if (p > l) bitonic_cmp(s, base + l, base + p, l, p, k);
        }
        __syncthreads();
    }
    for (int t = tid; t < 2048; t += 1024) g_keys[base + t] = s[t];
}

// ---------------- 3. gather sx/sp, pack (x,y,z,|p|^2) ----------------
__global__ void k_gather(const float* __restrict__ x, const float* __restrict__ pos) {
    int t = blockIdx.x * blockDim.x + threadIdx.x;
    if (t < NS * D) {
        int r = t >> 6, d = t & 63;
        g_sx[t] = x[sel_of(r) * D + d];
    }
    if (t < NS * 3) {
        int r = t / 3, c = t % 3;
        g_sp[t] = pos[sel_of(r) * 3 + c];
    }
    if (t < NS) {
        int sI = sel_of(t);
        float a = pos[sI * 3], b = pos[sI * 3 + 1], c = pos[sI * 3 + 2];
        float sq = __fadd_rn(__fadd_rn(__fmul_rn(a, a), __fmul_rn(b, b)), __fmul_rn(c, c));
        g_sp4[t] = make_float4(a, b, c, sq);
    }
}

// ---------------- 4. spatial 15-NN, warp per i ----------------
__global__ void k_knn_space() {
    int i = (blockIdx.x * blockDim.x + threadIdx.x) >> 5;
    int lane = threadIdx.x & 31;
    if (i >= NS) return;
    float4 pi = g_sp4[i];
    float bd[EK]; int bi[EK];
#pragma unroll
    for (int t = 0; t < EK; t++) { bd[t] = INFINITY; bi[t] = 0x7FFFFFFF; }
    for (int j = lane; j < NS; j += 32) {
        if (j == i) continue;
        float4 p = g_sp4[j];
        float dot = fmaf(pi.z, p.z, fmaf(pi.y, p.y, __fmul_rn(pi.x, p.x)));
        float d2 = __fsub_rn(__fadd_rn(pi.w, p.w), __fmul_rn(2.0f, dot));
        if (d2 < bd[EK - 1]) {      // strict <: ascending-j arrival keeps earliest on ties
            bd[EK - 1] = d2; bi[EK - 1] = j;
#pragma unroll
            for (int t2 = EK - 1; t2 > 0; t2--) {
                if (bd[t2] < bd[t2 - 1]) {
                    float a = bd[t2]; bd[t2] = bd[t2 - 1]; bd[t2 - 1] = a;
                    int   b = bi[t2]; bi[t2] = bi[t2 - 1]; bi[t2 - 1] = b;
                }
            }
        }
    }
    // warp merge: 15 rounds of lexicographic (d2, j) argmin via packed u64
#pragma unroll 1
    for (int r = 0; r < EK; r++) {
        unsigned long long key =
            ((unsigned long long)f32_sortable(bd[0]) << 32) | (unsigned int)bi[0];
        unsigned long long kk = key;
#pragma unroll
        for (int o = 16; o > 0; o >>= 1) {
            unsigned long long o2 = __shfl_xor_sync(0xffffffffu, kk, o);
            if (o2 < kk) kk = o2;
        }
        if (lane == 0) g_nbr[i * EK + r] = (int)(kk & 0xFFFFFFFFull);
        if (key == kk) {   // unique owner pops (j unique per lane)
#pragma unroll
            for (int q = 0; q < EK - 1; q++) { bd[q] = bd[q + 1]; bi[q] = bi[q + 1]; }
            bd[EK - 1] = INFINITY; bi[EK - 1] = 0x7FFFFFFF;
        }
    }
}

// ---------------- 5. zero dense adj ----------------
__global__ void k_zero() {
    size_t t = (size_t)blockIdx.x * blockDim.x + threadIdx.x;
    float4* p = (float4*)g_adj;
    size_t n = (size_t)NS * NS / 4;
    for (size_t q = t; q < n; q += (size_t)gridDim.x * blockDim.x)
        p[q] = make_float4(0.f, 0.f, 0.f, 0.f);
}

// ---------------- 6. edge probs -> symmetric adjacency ----------------
__global__ void k_edges(const float* __restrict__ w_e) {
    __shared__ float swe[D];
    if (threadIdx.x < D) swe[threadIdx.x] = w_e[threadIdx.x];
    __syncthreads();
    int e = blockIdx.x * blockDim.x + threadIdx.x;
    if (e >= NS * EK) return;
    int i = e / EK;
    int j = g_nbr[e];
    const float* a = g_sx + i * D;
    const float* b = g_sx + j * D;
    float acc = 0.0f;
#pragma unroll 8
    for (int d = 0; d < D; d++)
        acc = fmaf(__fmul_rn(a[d], b[d]), swe[d], acc);   // bitwise symmetric in (i,j)
    float ep = sigmoid_exact(acc);
    g_adj[(size_t)i * NS + j] = ep;
    g_adj[(size_t)j * NS + i] = ep;
}

// ---------------- 7. CSR support per row (ascending j), 1 warp/row ----------------
__global__ void k_supp() {
    int warp = (blockIdx.x * blockDim.x + threadIdx.x) >> 5;
    int lane = threadIdx.x & 31;
    if (warp >= NS) return;
    const float* row = g_adj + (size_t)warp * NS;
    int cnt = 0;
    for (int base = 0; base < NS; base += 32) {
        float v = row[base + lane];
        unsigned m = __ballot_sync(0xffffffffu, v != 0.0f);
        if (v != 0.0f) {
            int pos = cnt + __popc(m & ((1u << lane) - 1u));
            if (pos < MAXD) { g_scol[warp * MAXD + pos] = base + lane; g_sval[warp * MAXD + pos] = v; }
        }
        cnt += __popc(m);
    }
    if (lane == 0) g_deg[warp] = min(cnt, MAXD);
}

// ---------------- 8. row norms (ascending sequential; zeros exact no-ops) ----------------
__global__ void k_norm() {
    int i = blockIdx.x * blockDim.x + threadIdx.x;
    if (i >= NS) return;
    int dg = g_deg[i];
    const float* v = g_sval + i * MAXD;
    float s = 0.0f;
    for (int t = 0; t < dg; t++) s = __fadd_rn(s, __fmul_rn(v[t], v[t]));
    g_norm[i] = s;
}

// ---------------- 9. fd2 top-16 via deterministic scatter SpGEMM (1 block/row) ----------------
// dot_ij accumulates over k ascending (sequential u-steps) — bitwise identical to the
// reference dense ascending-k fma chain (zero terms are exact fma no-ops).
__global__ void k_fd2() {
    __shared__ float sdot[NS];          // 16 KB
    __shared__ int   scol[MAXD];
    __shared__ float sval[MAXD];
    __shared__ unsigned long long swin[4];
    int i = blockIdx.x, tid = threadIdx.x;       // 128 threads
    int dg = g_deg[i];
    for (int t = tid; t < NS; t += 128) sdot[t] = 0.0f;
    for (int t = tid; t < dg; t += 128) { scol[t] = g_scol[i * MAXD + t]; sval[t] = g_sval[i * MAXD + t]; }
    __syncthreads();
    for (int u = 0; u < dg; u++) {               // ascending k
        int k = scol[u];
        float aik = sval[u];
        int dk = g_deg[k];
        const int*   ck = g_scol + k * MAXD;
        const float* cv = g_sval + k * MAXD;
        for (int t = tid; t < dk; t += 128) {    // distinct j's: race-free
            int j = ck[t];
            sdot[j] = fmaf(aik, cv[t], sdot[j]);
        }
        __syncthreads();
    }
    float ni = g_norm[i];
    float bd[KNN]; int bj[KNN];
#pragma unroll
    for (int t = 0; t < KNN; t++) { bd[t] = INFINITY; bj[t] = 0x7FFFFFFF; }
    for (int j = tid; j < NS; j += 128) {
        if (j == i) continue;
        float fd2 = __fsub_rn(__fadd_rn(ni, g_norm[j]), __fmul_rn(2.0f, sdot[j]));
        if (fd2 < bd[KNN - 1]) {
            bd[KNN - 1] = fd2; bj[KNN - 1] = j;
#pragma unroll
            for (int t2 = KNN - 1; t2 > 0; t2--) {
                if (bd[t2] < bd[t2 - 1]) {
                    float a = bd[t2]; bd[t2] = bd[t2 - 1]; bd[t2 - 1] = a;
                    int   b = bj[t2]; bj[t2] = bj[t2 - 1]; bj[t2 - 1] = b;
                }
            }
        }
    }
    __syncthreads();
    int wid = tid >> 5, lane = tid & 31;
#pragma unroll 1
    for (int r = 0; r < KNN; r++) {
        unsigned long long key =
            ((unsigned long long)f32_sortable(bd[0]) << 32) | (unsigned int)bj[0];
        unsigned long long kk = key;
#pragma unroll
        for (int o = 16; o > 0; o >>= 1) {
            unsigned long long o2 = __shfl_xor_sync(0xffffffffu, kk, o);
            if (o2 < kk) kk = o2;
        }
        if (lane == 0) swin[wid] = kk;
        __syncthreads();
        unsigned long long w = swin[0];
#pragma unroll
        for (int q = 1; q < 4; q++) if (swin[q] < w) w = swin[q];
        if (tid == 0) g_knn[i * KNN + r] = (int)(w & 0xFFFFFFFFull);
        if (key == w) {    // unique owner pops (j unique per thread)
#pragma unroll
            for (int q = 0; q < KNN - 1; q++) { bd[q] = bd[q + 1]; bj[q] = bj[q + 1]; }
            bd[KNN - 1] = INFINITY; bj[KNN - 1] = 0x7FFFFFFF;
        }
        __syncthreads();
    }
}

// ---------------- 10. per-vertex MLP projection p_v = [sx_v, sp_v] @ Wf1 ----------------
__global__ void k_pfeat(const float* __restrict__ Wf1) {
    __shared__ float sW[(D + 3) * H];
    int tid = threadIdx.x;
    for (int t = tid; t < (D + 3) * H; t += blockDim.x) sW[t] = Wf1[t];
    __syncthreads();
    int warp = (blockIdx.x * blockDim.x + tid) >> 5;
    int lane = tid & 31;
    if (warp >= NS) return;
    float acc[4] = {0.f, 0.f, 0.f, 0.f};
#pragma unroll 8
    for (int d = 0; d < D; d++) {
        float xv = g_sx[warp * D + d];
#pragma unroll
        for (int q = 0; q < 4; q++) acc[q] = fmaf(xv, sW[d * H + lane + q * 32], acc[q]);
    }
#pragma unroll
    for (int c = 0; c < 3; c++) {
        float pv = g_sp[warp * 3 + c];
#pragma unroll
        for (int q = 0; q < 4; q++) acc[q] = fmaf(pv, sW[(D + c) * H + lane + q * 32], acc[q]);
    }
#pragma unroll
    for (int q = 0; q < 4; q++) g_p[warp * H + lane + q * 32] = acc[q];
}

// ---------------- 11. triangles: fprob/tprob (1 block/row, thread/pair) ----------------
__global__ void k_tri(const float* __restrict__ bf1, const float* __restrict__ wf2,
                      float* __restrict__ out) {
    __shared__ float spn[KNN * 132];
    __shared__ float spi[H];
    __shared__ float sb[H];
    __shared__ float sw[H];
    __shared__ int   sknn[KNN];
    __shared__ float sain[KNN];
    int i = blockIdx.x, tid = threadIdx.x;
    if (tid < KNN) sknn[tid] = g_knn[i * KNN + tid];
    if (tid < H) { spi[tid] = g_p[i * H + tid]; sb[tid] = bf1[tid]; sw[tid] = wf2[tid]; }
    __syncthreads();
    for (int t = tid; t < KNN * H; t += 128) {
        int r = t >> 7, h = t & 127;
        spn[r * 132 + h] = g_p[sknn[r] * H + h];
    }
    if (tid < KNN) sain[tid] = g_adj[(size_t)i * NS + sknn[tid]];
    __syncthreads();
    if (tid < NPAIR) {
        int rem = tid, jj = 0;
        while (rem >= EK - jj) { rem -= EK - jj; jj++; }
        int ll = jj + 1 + rem;
        int n1 = sknn[jj], n2 = sknn[ll];
        float a12 = g_adj[(size_t)n1 * NS + n2];
        const float* p1 = spn + jj * 132;
        const float* p2 = spn + ll * 132;
        float acc = 0.0f;
#pragma unroll 8
        for (int h = 0; h < H; h++) {
            float pre = __fadd_rn(__fdiv_rn(__fadd_rn(__fadd_rn(spi[h], p1[h]), p2[h]), 3.0f),
                                  sb[h]);
            acc = fmaf(fmaxf(pre, 0.0f), sw[h], acc);
        }
        float valid = (a12 > 0.0f) ? 1.0f : 0.0f;
        float fp = sigmoid_fast(acc) * valid;
        float prod = __fmul_rn(__fmul_rn(sain[jj], sain[ll]), a12);
        float tp = (a12 > 0.0f) ? cbrtf(fmaxf(prod, 1e-9f)) : 0.0f;
        out[(size_t)i * NPAIR + tid]                      = fp;
        out[(size_t)NS * NPAIR + (size_t)i * NPAIR + tid] = tp;
    }
}

// ---------------- launch ----------------
extern "C" void kernel_launch(void* const* d_in, const int* in_sizes, int n_in,
                              void* d_out, int out_size) {
    const float* x   = (const float*)d_in[0];
    const float* pos = (const float*)d_in[1];
    const float* W1  = (const float*)d_in[2];
    const float* b1  = (const float*)d_in[3];
    const float* w2  = (const float*)d_in[4];
    const float* w_e = (const float*)d_in[5];
    const float* Wf1 = (const float*)d_in[6];
    const float* bf1 = (const float*)d_in[7];
    const float* wf2 = (const float*)d_in[8];
    float* out = (float*)d_out;

    k_zero<<<512, 256>>>();
    k_logits<<<(N_IN * 32 + 255) / 256, 256>>>(x, W1, b1, w2);
    k_keys<<<NSORT / 256, 256>>>();
    k_sortL1<<<4, 1024>>>();
    k_sortG<<<NSORT / 256, 256>>>(4096, 2048);
    k_sortT<<<4, 1024>>>(4096);
    k_sortG<<<NSORT / 256, 256>>>(8192, 4096);
    k_sortG<<<NSORT / 256, 256>>>(8192, 2048);
    k_sortT<<<4, 1024>>>(8192);
    k_gather<<<(NS * D + 255) / 256, 256>>>(x, pos);
    k_knn_space<<<(NS * 32 + 255) / 256, 256>>>();
    k_edges<<<(NS * EK + 255) / 256, 256>>>(w_e);
    k_supp<<<(NS * 32 + 255) / 256, 256>>>();
    k_norm<<<(NS + 255) / 256, 256>>>();
    k_fd2<<<NS, 128>>>();
    k_pfeat<<<(NS * 32 + 255) / 256, 256>>>(Wf1);
    k_tri<<<NS, 128>>>(bf1, wf2, out);
}

// round 5
// speedup vs baseline: 2.2344x; 1.0552x over previous
#include <cuda_runtime.h>
#include <math.h>

#define N_IN  8000
#define NS    4000
#define D     64
#define H     128
#define EK    15
#define KNN   16
#define NPAIR 120
#define MAXD  256

// ---------------- scratch (no allocations allowed) ----------------
__device__ float g_prob[N_IN];
__device__ int   g_sel[NS];
__device__ int   g_cnt[NS];
__device__ float g_sx[NS * D];
__device__ float g_sp[NS * 3];
__device__ float4 g_sp4[NS];
__device__ int   g_nbr[NS * EK];
__device__ int   g_deg[NS];
__device__ int   g_scol[NS * MAXD];    // unsorted buckets, then sorted CSR (in place)
__device__ float g_sval[NS * MAXD];
__device__ float g_norm[NS];
__device__ int   g_knn[NS * KNN];
__device__ float g_p[NS * H];

__device__ __forceinline__ float sigmoid_fast(float v) { return 1.0f / (1.0f + expf(-v)); }
// near-correctly-rounded fp32 sigmoid — matches libm expf bits
__device__ __forceinline__ float sigmoid_exact(float v) {
    float e = (float)exp(-(double)v);
    return __fdiv_rn(1.0f, __fadd_rn(1.0f, e));
}
__device__ __forceinline__ unsigned int f32_sortable(float f) {
    unsigned int b = __float_as_uint(f);
    return (b & 0x80000000u) ? ~b : (b | 0x80000000u);
}
// sorted-CSR point lookup (rows ascending in j)
__device__ __forceinline__ float adj_lookup(int r, int j) {
    const int* c = g_scol + r * MAXD;
    int n = g_deg[r];
    int lo = 0, hi = n;
    while (lo < hi) { int mid = (lo + hi) >> 1; if (c[mid] < j) lo = mid + 1; else hi = mid; }
    return (lo < n && c[lo] == j) ? g_sval[r * MAXD + lo] : 0.0f;
}

// ---------------- 1. probs = sigmoid(relu(x@W1 + b1) @ w2), Eigen bit-model ----------------
__global__ void k_logits(const float* __restrict__ x, const float* __restrict__ W1,
                         const float* __restrict__ b1, const float* __restrict__ w2) {
    __shared__ float sW[D * H];
    __shared__ float sw2[H];
    __shared__ float sb1[H];
    __shared__ float sh[8][H];
    int tid = threadIdx.x;
    for (int t = tid; t < D * H; t += blockDim.x) sW[t] = W1[t];
    if (tid < H) { sw2[tid] = w2[tid]; sb1[tid] = b1[tid]; }
    __syncthreads();
    int warp = (blockIdx.x * blockDim.x + tid) >> 5;
    int wloc = (tid >> 5);
    int lane = tid & 31;
    if (warp >= N_IN) return;
    const float* xr = x + warp * D;
    float acc[4] = {0.f, 0.f, 0.f, 0.f};
#pragma unroll 8
    for (int d = 0; d < D; d++) {
        float xv = xr[d];
#pragma unroll
        for (int q = 0; q < 4; q++) acc[q] = fmaf(xv, sW[d * H + lane + q * 32], acc[q]);
    }
#pragma unroll
    for (int q = 0; q < 4; q++) {
        int j = lane + q * 32;
        sh[wloc][j] = fmaxf(__fadd_rn(acc[q], sb1[j]), 0.0f);
    }
    __syncwarp();
    if (lane == 0) {
        float logit = 0.0f;
#pragma unroll 8
        for (int j = 0; j < H; j++) logit = fmaf(sh[wloc][j], sw2[j], logit);
        g_prob[warp] = sigmoid_exact(logit);
    }
}

// ---------------- 2. rank-select: sel[rank] = i (desc prob, asc-index ties) ----------------
__global__ void k_rank() {
    __shared__ float sp[N_IN];      // 32 KB
    int tid = threadIdx.x;
    int i = blockIdx.x * blockDim.x + tid;
    for (int t = tid; t < N_IN; t += blockDim.x) sp[t] = g_prob[t];
    __syncthreads();
    if (i < NS) g_cnt[i] = 0;       // zero CSR counters for k_edges
    if (i >= N_IN) return;
    float pi = sp[i];
    int r = 0;
#pragma unroll 8
    for (int j = 0; j < N_IN; j++) {
        float pj = sp[j];
        r += (pj > pi) || (pj == pi && j < i);
    }
    if (r < NS) g_sel[r] = i;
}

// ---------------- 3. gather sx/sp, pack (x,y,z,|p|^2) ----------------
__global__ void k_gather(const float* __restrict__ x, const float* __restrict__ pos) {
    int t = blockIdx.x * blockDim.x + threadIdx.x;
    if (t < NS * D) {
        int r = t >> 6, d = t & 63;
        g_sx[t] = x[g_sel[r] * D + d];
    }
    if (t < NS * 3) {
        int r = t / 3, c = t % 3;
        g_sp[t] = pos[g_sel[r] * 3 + c];
    }
    if (t < NS) {
        int sI = g_sel[t];
        float a = pos[sI * 3], b = pos[sI * 3 + 1], c = pos[sI * 3 + 2];
        float sq = __fadd_rn(__fadd_rn(__fmul_rn(a, a), __fmul_rn(b, b)), __fmul_rn(c, c));
        g_sp4[t] = make_float4(a, b, c, sq);
    }
}

// ---------------- 4. spatial 15-NN, warp per i ----------------
__global__ void k_knn_space() {
    int i = (blockIdx.x * blockDim.x + threadIdx.x) >> 5;
    int lane = threadIdx.x & 31;
    if (i >= NS) return;
    float4 pi = g_sp4[i];
    float bd[EK]; int bi[EK];
#pragma unroll
    for (int t = 0; t < EK; t++) { bd[t] = INFINITY; bi[t] = 0x7FFFFFFF; }
    for (int j = lane; j < NS; j += 32) {
        if (j == i) continue;
        float4 p = g_sp4[j];
        float dot = fmaf(pi.z, p.z, fmaf(pi.y, p.y, __fmul_rn(pi.x, p.x)));
        float d2 = __fsub_rn(__fadd_rn(pi.w, p.w), __fmul_rn(2.0f, dot));
        if (d2 < bd[EK - 1]) {
            bd[EK - 1] = d2; bi[EK - 1] = j;
#pragma unroll
            for (int t2 = EK - 1; t2 > 0; t2--) {
                if (bd[t2] < bd[t2 - 1]) {
                    float a = bd[t2]; bd[t2] = bd[t2 - 1]; bd[t2 - 1] = a;
                    int   b = bi[t2]; bi[t2] = bi[t2 - 1]; bi[t2 - 1] = b;
                }
            }
        }
    }
#pragma unroll 1
    for (int r = 0; r < EK; r++) {
        unsigned long long key =
            ((unsigned long long)f32_sortable(bd[0]) << 32) | (unsigned int)bi[0];
        unsigned long long kk = key;
#pragma unroll
        for (int o = 16; o > 0; o >>= 1) {
            unsigned long long o2 = __shfl_xor_sync(0xffffffffu, kk, o);
            if (o2 < kk) kk = o2;
        }
        if (lane == 0) g_nbr[i * EK + r] = (int)(kk & 0xFFFFFFFFull);
        if (key == kk) {
#pragma unroll
            for (int q = 0; q < EK - 1; q++) { bd[q] = bd[q + 1]; bi[q] = bi[q + 1]; }
            bd[EK - 1] = INFINITY; bi[EK - 1] = 0x7FFFFFFF;
        }
    }
}

// ---------------- 5. edge probs -> scatter into per-row buckets ----------------
__global__ void k_edges(const float* __restrict__ w_e) {
    __shared__ float swe[D];
    if (threadIdx.x < D) swe[threadIdx.x] = w_e[threadIdx.x];
    __syncthreads();
    int e = blockIdx.x * blockDim.x + threadIdx.x;
    if (e >= NS * EK) return;
    int i = e / EK;
    int j = g_nbr[e];
    const float* a = g_sx + i * D;
    const float* b = g_sx + j * D;
    float acc = 0.0f;
#pragma unroll 8
    for (int d = 0; d < D; d++)
        acc = fmaf(__fmul_rn(a[d], b[d]), swe[d], acc);   // bitwise symmetric in (i,j)
    float ep = sigmoid_exact(acc);
    int p1 = atomicAdd(&g_cnt[i], 1);
    if (p1 < MAXD) { g_scol[i * MAXD + p1] = j; g_sval[i * MAXD + p1] = ep; }
    int p2 = atomicAdd(&g_cnt[j], 1);
    if (p2 < MAXD) { g_scol[j * MAXD + p2] = i; g_sval[j * MAXD + p2] = ep; }
}

// ---------------- 6. per-row: sort by j, dedup, norm, deg (warp/row) ----------------
__global__ void k_rowsort() {
    __shared__ int   sj[4][MAXD];
    __shared__ float sv[4][MAXD];
    int gw   = (blockIdx.x * blockDim.x + threadIdx.x) >> 5;
    int wloc = (threadIdx.x >> 5);
    int lane = threadIdx.x & 31;
    if (gw >= NS) return;
    int n = min(g_cnt[gw], MAXD);
    int*   mj = sj[wloc];
    float* mv = sv[wloc];
    for (int t = lane; t < n; t += 32) { mj[t] = g_scol[gw * MAXD + t]; mv[t] = g_sval[gw * MAXD + t]; }
    __syncwarp();
    // rank with (j, slot) key: stable ascending-j sort
    int   jr[8]; float vr[8]; int rr[8]; int ne = 0;
    for (int t = lane; t < n; t += 32) {
        int jt = mj[t]; float vt = mv[t];
        int r = 0;
        for (int m = 0; m < n; m++) {
            int jm = mj[m];
            r += (jm < jt) || (jm == jt && m < t);
        }
        jr[ne] = jt; vr[ne] = vt; rr[ne] = r; ne++;
    }
    __syncwarp();
    for (int q = 0; q < ne; q++) { mj[rr[q]] = jr[q]; mv[rr[q]] = vr[q]; }
    __syncwarp();
    if (lane == 0) {
        int cnt = 0, prev = -1;
        float s = 0.0f;
        for (int t = 0; t < n; t++) {
            int jt = mj[t];
            if (jt != prev) {
                float vt = mv[t];
                g_scol[gw * MAXD + cnt] = jt;
                g_sval[gw * MAXD + cnt] = vt;
                s = __fadd_rn(s, __fmul_rn(vt, vt));   // ascending-j chain
                cnt++; prev = jt;
            }
        }
        g_deg[gw] = cnt;
        g_norm[gw] = s;
    }
}

// ---------------- 7. fd2 top-16 via deterministic scatter SpGEMM (1 block/row) ----------------
// ascending-k sequential steps -> bitwise identical to reference dense fma chain
__global__ void k_fd2() {
    __shared__ float sdot[NS];          // 16 KB
    __shared__ int   scol[MAXD];
    __shared__ float sval[MAXD];
    __shared__ unsigned long long swin[4];
    int i = blockIdx.x, tid = threadIdx.x;       // 128 threads
    int dg = g_deg[i];
    for (int t = tid; t < NS; t += 128) sdot[t] = 0.0f;
    for (int t = tid; t < dg; t += 128) { scol[t] = g_scol[i * MAXD + t]; sval[t] = g_sval[i * MAXD + t]; }
    __syncthreads();
    // software-pipelined scatter: prefetch next row's entries before the barrier
    int jn0 = 0, jn1 = 0; float vn0 = 0.f, vn1 = 0.f; int dk_cur = 0;
    if (dg > 0) {
        int k = scol[0];
        dk_cur = g_deg[k];
        const int* ck = g_scol + k * MAXD; const float* cv = g_sval + k * MAXD;
        if (tid < dk_cur)        { jn0 = ck[tid];        vn0 = cv[tid]; }
        if (tid + 128 < dk_cur)  { jn1 = ck[tid + 128];  vn1 = cv[tid + 128]; }
    }
    for (int u = 0; u < dg; u++) {
        float aik = sval[u];
        int j20 = 0, j21 = 0; float v20 = 0.f, v21 = 0.f; int dk_next = 0;
        if (u + 1 < dg) {
            int k2 = scol[u + 1];
            dk_next = g_deg[k2];
            const int* ck = g_scol + k2 * MAXD; const float* cv = g_sval + k2 * MAXD;
            if (tid < dk_next)       { j20 = ck[tid];       v20 = cv[tid]; }
            if (tid + 128 < dk_next) { j21 = ck[tid + 128]; v21 = cv[tid + 128]; }
        }
        if (tid < dk_cur)       sdot[jn0] = fmaf(aik, vn0, sdot[jn0]);
        if (tid + 128 < dk_cur) sdot[jn1] = fmaf(aik, vn1, sdot[jn1]);
        __syncthreads();
        dk_cur = dk_next; jn0 = j20; vn0 = v20; jn1 = j21; vn1 = v21;
    }
    float ni = g_norm[i];
    float bd[KNN]; int bj[KNN];
#pragma unroll
    for (int t = 0; t < KNN; t++) { bd[t] = INFINITY; bj[t] = 0x7FFFFFFF; }
    for (int j = tid; j < NS; j += 128) {
        if (j == i) continue;
        float fd2 = __fsub_rn(__fadd_rn(ni, g_norm[j]), __fmul_rn(2.0f, sdot[j]));
        if (fd2 < bd[KNN - 1]) {
            bd[KNN - 1] = fd2; bj[KNN - 1] = j;
#pragma unroll
            for (int t2 = KNN - 1; t2 > 0; t2--) {
                if (bd[t2] < bd[t2 - 1]) {
                    float a = bd[t2]; bd[t2] = bd[t2 - 1]; bd[t2 - 1] = a;
                    int   b = bj[t2]; bj[t2] = bj[t2 - 1]; bj[t2 - 1] = b;
                }
            }
        }
    }
    __syncthreads();
    int wid = tid >> 5, lane = tid & 31;
#pragma unroll 1
    for (int r = 0; r < KNN; r++) {
        unsigned long long key =
            ((unsigned long long)f32_sortable(bd[0]) << 32) | (unsigned int)bj[0];
        unsigned long long kk = key;
#pragma unroll
        for (int o = 16; o > 0; o >>= 1) {
            unsigned long long o2 = __shfl_xor_sync(0xffffffffu, kk, o);
            if (o2 < kk) kk = o2;
        }
        if (lane == 0) swin[wid] = kk;
        __syncthreads();
        unsigned long long w = swin[0];
#pragma unroll
        for (int q = 1; q < 4; q++) if (swin[q] < w) w = swin[q];
        if (tid == 0) g_knn[i * KNN + r] = (int)(w & 0xFFFFFFFFull);
        if (key == w) {
#pragma unroll
            for (int q = 0; q < KNN - 1; q++) { bd[q] = bd[q + 1]; bj[q] = bj[q + 1]; }
            bd[KNN - 1] = INFINITY; bj[KNN - 1] = 0x7FFFFFFF;
        }
        __syncthreads();
    }
}

// ---------------- 8. per-vertex MLP projection p_v = [sx_v, sp_v] @ Wf1 ----------------
__global__ void k_pfeat(const float* __restrict__ Wf1) {
    __shared__ float sW[(D + 3) * H];
    int tid = threadIdx.x;
    for (int t = tid; t < (D + 3) * H; t += blockDim.x) sW[t] = Wf1[t];
    __syncthreads();
    int warp = (blockIdx.x * blockDim.x + tid) >> 5;
    int lane = tid & 31;
    if (warp >= NS) return;
    float acc[4] = {0.f, 0.f, 0.f, 0.f};
#pragma unroll 8
    for (int d = 0; d < D; d++) {
        float xv = g_sx[warp * D + d];
#pragma unroll
        for (int q = 0; q < 4; q++) acc[q] = fmaf(xv, sW[d * H + lane + q * 32], acc[q]);
    }
#pragma unroll
    for (int c = 0; c < 3; c++) {
        float pv = g_sp[warp * 3 + c];
#pragma unroll
        for (int q = 0; q < 4; q++) acc[q] = fmaf(pv, sW[(D + c) * H + lane + q * 32], acc[q]);
    }
#pragma unroll
    for (int q = 0; q < 4; q++) g_p[warp * H + lane + q * 32] = acc[q];
}

// ---------------- 9. triangles: fprob/tprob (1 block/row, thread/pair) ----------------
__global__ void k_tri(const float* __restrict__ bf1, const float* __restrict__ wf2,
                      float* __restrict__ out) {
    __shared__ float spn[KNN * 132];
    __shared__ float spi[H];
    __shared__ float sb[H];
    __shared__ float sw[H];
    __shared__ int   sknn[KNN];
    __shared__ float sain[KNN];
    int i = blockIdx.x, tid = threadIdx.x;
    if (tid < KNN) sknn[tid] = g_knn[i * KNN + tid];
    if (tid < H) { spi[tid] = g_p[i * H + tid]; sb[tid] = bf1[tid]; sw[tid] = wf2[tid]; }
    __syncthreads();
    for (int t = tid; t < KNN * H; t += 128) {
        int r = t >> 7, h = t & 127;
        spn[r * 132 + h] = g_p[sknn[r] * H + h];
    }
    if (tid < KNN) sain[tid] = adj_lookup(i, sknn[tid]);
    __syncthreads();
    if (tid < NPAIR) {
        int rem = tid, jj = 0;
        while (rem >= EK - jj) { rem -= EK - jj; jj++; }
        int ll = jj + 1 + rem;
        int n1 = sknn[jj], n2 = sknn[ll];
        float a12 = adj_lookup(n1, n2);
        const float* p1 = spn + jj * 132;
        const float* p2 = spn + ll * 132;
        float acc = 0.0f;
#pragma unroll 8
        for (int h = 0; h < H; h++) {
            float pre = __fadd_rn(__fdiv_rn(__fadd_rn(__fadd_rn(spi[h], p1[h]), p2[h]), 3.0f),
                                  sb[h]);
            acc = fmaf(fmaxf(pre, 0.0f), sw[h], acc);
        }
        float valid = (a12 > 0.0f) ? 1.0f : 0.0f;
        float fp = sigmoid_fast(acc) * valid;
        float prod = __fmul_rn(__fmul_rn(sain[jj], sain[ll]), a12);
        float tp = (a12 > 0.0f) ? cbrtf(fmaxf(prod, 1e-9f)) : 0.0f;
        out[(size_t)i * NPAIR + tid]                      = fp;
        out[(size_t)NS * NPAIR + (size_t)i * NPAIR + tid] = tp;
    }
}

// ---------------- launch ----------------
extern "C" void kernel_launch(void* const* d_in, const int* in_sizes, int n_in,
                              void* d_out, int out_size) {
    const float* x   = (const float*)d_in[0];
    const float* pos = (const float*)d_in[1];
    const float* W1  = (const float*)d_in[2];
    const float* b1  = (const float*)d_in[3];
    const float* w2  = (const float*)d_in[4];
    const float* w_e = (const float*)d_in[5];
    const float* Wf1 = (const float*)d_in[6];
    const float* bf1 = (const float*)d_in[7];
    const float* wf2 = (const float*)d_in[8];
    float* out = (float*)d_out;

    k_logits<<<(N_IN * 32 + 255) / 256, 256>>>(x, W1, b1, w2);
    k_rank<<<(N_IN + 255) / 256, 256>>>();
    k_gather<<<(NS * D + 255) / 256, 256>>>(x, pos);
    k_knn_space<<<(NS * 32 + 255) / 256, 256>>>();
    k_edges<<<(NS * EK + 255) / 256, 256>>>(w_e);
    k_rowsort<<<(NS * 32 + 127) / 128, 128>>>();
    k_fd2<<<NS, 128>>>();
    k_pfeat<<<(NS * 32 + 255) / 256, 256>>>(Wf1);
    k_tri<<<NS, 128>>>(bf1, wf2, out);
}

// round 7
// speedup vs baseline: 2.5719x; 1.1511x over previous
#include <cuda_runtime.h>
#include <math.h>

#define N_IN  8000
#define NS    4000
#define D     64
#define H     128
#define EK    15
#define KNN   16
#define NPAIR 120
#define MAXD  256
#define GRID  16
#define NCELL (GRID * GRID * GRID)

// ---------------- scratch (no allocations allowed) ----------------
__device__ float g_prob[N_IN];
__device__ int   g_sel[NS];
__device__ int   g_cnt[NS];
__device__ float g_sx[NS * D];
__device__ float g_sp[NS * 3];
__device__ float4 g_sp4[NS];
__device__ int   g_nbr[NS * EK];
__device__ int   g_deg[NS];
__device__ int   g_scol[NS * MAXD];    // unsorted buckets, then sorted CSR (in place)
__device__ float g_sval[NS * MAXD];
__device__ float g_norm[NS];
__device__ int   g_knn[NS * KNN];
__device__ float g_p[NS * H];
// spatial grid
__device__ int   g_ccnt[NCELL];
__device__ int   g_cstart[NCELL];
__device__ int   g_pcell[NS];
__device__ int   g_pslot[NS];
__device__ int   g_cpts[NS];

__device__ __forceinline__ float sigmoid_fast(float v) { return 1.0f / (1.0f + expf(-v)); }
// near-correctly-rounded fp32 sigmoid — matches libm expf bits
__device__ __forceinline__ float sigmoid_exact(float v) {
    float e = (float)exp(-(double)v);
    return __fdiv_rn(1.0f, __fadd_rn(1.0f, e));
}
__device__ __forceinline__ unsigned int f32_sortable(float f) {
    unsigned int b = __float_as_uint(f);
    return (b & 0x80000000u) ? ~b : (b | 0x80000000u);
}
// sorted-CSR point lookup (rows ascending in j)
__device__ __forceinline__ float adj_lookup(int r, int j) {
    const int* c = g_scol + r * MAXD;
    int n = g_deg[r];
    int lo = 0, hi = n;
    while (lo < hi) { int mid = (lo + hi) >> 1; if (c[mid] < j) lo = mid + 1; else hi = mid; }
    return (lo < n && c[lo] == j) ? g_sval[r * MAXD + lo] : 0.0f;
}

// ---------------- 1. probs = sigmoid(relu(x@W1 + b1) @ w2), Eigen bit-model ----------------
__global__ void k_logits(const float* __restrict__ x, const float* __restrict__ W1,
                         const float* __restrict__ b1, const float* __restrict__ w2) {
    __shared__ float sW[D * H];
    __shared__ float sw2[H];
    __shared__ float sb1[H];
    __shared__ float sh[8][H];
    int tid = threadIdx.x;
    for (int t = tid; t < D * H; t += blockDim.x) sW[t] = W1[t];
    if (tid < H) { sw2[tid] = w2[tid]; sb1[tid] = b1[tid]; }
    __syncthreads();
    int warp = (blockIdx.x * blockDim.x + tid) >> 5;
    int wloc = (tid >> 5);
    int lane = tid & 31;
    if (warp >= N_IN) return;
    const float* xr = x + warp * D;
    float acc[4] = {0.f, 0.f, 0.f, 0.f};
#pragma unroll 8
    for (int d = 0; d < D; d++) {
        float xv = xr[d];
#pragma unroll
        for (int q = 0; q < 4; q++) acc[q] = fmaf(xv, sW[d * H + lane + q * 32], acc[q]);
    }
#pragma unroll
    for (int q = 0; q < 4; q++) {
        int j = lane + q * 32;
        sh[wloc][j] = fmaxf(__fadd_rn(acc[q], sb1[j]), 0.0f);
    }
    __syncwarp();
    if (lane == 0) {
        float logit = 0.0f;
#pragma unroll 8
        for (int j = 0; j < H; j++) logit = fmaf(sh[wloc][j], sw2[j], logit);
        g_prob[warp] = sigmoid_exact(logit);
    }
}

// ---------------- 2. rank-select: sel[rank] = i; zero counters ----------------
__global__ void k_rank() {
    __shared__ float sp[N_IN];      // 32 KB
    int tid = threadIdx.x;
    int i = blockIdx.x * blockDim.x + tid;
    for (int t = tid; t < N_IN; t += blockDim.x) sp[t] = g_prob[t];
    __syncthreads();
    if (i < NS) g_cnt[i] = 0;
    if (i < NCELL) g_ccnt[i] = 0;
    if (i >= N_IN) return;
    float pi = sp[i];
    int r = 0;
#pragma unroll 8
    for (int j = 0; j < N_IN; j++) {
        float pj = sp[j];
        r += (pj > pi) || (pj == pi && j < i);
    }
    if (r < NS) g_sel[r] = i;
}

// ---------------- 3. gather sx/sp, pack (x,y,z,|p|^2), grid-cell insert ----------------
__global__ void k_gather(const float* __restrict__ x, const float* __restrict__ pos) {
    int t = blockIdx.x * blockDim.x + threadIdx.x;
    if (t < NS * D) {
        int r = t >> 6, d = t & 63;
        g_sx[t] = x[g_sel[r] * D + d];
    }
    if (t < NS * 3) {
        int r = t / 3, c = t % 3;
        g_sp[t] = pos[g_sel[r] * 3 + c];
    }
    if (t < NS) {
        int sI = g_sel[t];
        float a = pos[sI * 3], b = pos[sI * 3 + 1], c = pos[sI * 3 + 2];
        float sq = __fadd_rn(__fadd_rn(__fmul_rn(a, a), __fmul_rn(b, b)), __fmul_rn(c, c));
        g_sp4[t] = make_float4(a, b, c, sq);
        int ix = min(GRID - 1, max(0, (int)(a * GRID)));
        int iy = min(GRID - 1, max(0, (int)(b * GRID)));
        int iz = min(GRID - 1, max(0, (int)(c * GRID)));
        int cell = ix + GRID * (iy + GRID * iz);
        g_pcell[t] = cell;
        g_pslot[t] = atomicAdd(&g_ccnt[cell], 1);
    }
}

// ---------------- 3b. exclusive scan over 4096 cell counts (1 block) ----------------
__global__ void k_cscan() {
    __shared__ int sa[NCELL];
    __shared__ int sb[NCELL];
    int tid = threadIdx.x;   // 1024
    for (int t = tid; t < NCELL; t += 1024) sa[t] = g_ccnt[t];
    __syncthreads();
    int* cur = sa; int* nxt = sb;
    for (int off = 1; off < NCELL; off <<= 1) {
        for (int t = tid; t < NCELL; t += 1024)
            nxt[t] = cur[t] + ((t >= off) ? cur[t - off] : 0);
        __syncthreads();
        int* tmp = cur; cur = nxt; nxt = tmp;
    }
    for (int t = tid; t < NCELL; t += 1024) g_cstart[t] = cur[t] - g_ccnt[t];
}

// ---------------- 3c. scatter points into cell lists ----------------
__global__ void k_cscatter() {
    int t = blockIdx.x * blockDim.x + threadIdx.x;
    if (t >= NS) return;
    g_cpts[g_cstart[g_pcell[t]] + g_pslot[t]] = t;
}

// ---------------- 4. grid-accelerated exact 15-NN, warp per i ----------------
// Selection via packed (d2, j) u64 keys -> enumeration-order independent,
// exactly top_k's (value, ascending-index) tie semantics.
__global__ void k_knn_space() {
    int i = (blockIdx.x * blockDim.x + threadIdx.x) >> 5;
    int lane = threadIdx.x & 31;
    if (i >= NS) return;
    float4 pi = g_sp4[i];
    int cx = min(GRID - 1, max(0, (int)(pi.x * GRID)));
    int cy = min(GRID - 1, max(0, (int)(pi.y * GRID)));
    int cz = min(GRID - 1, max(0, (int)(pi.z * GRID)));
    unsigned long long buf[EK];
#pragma unroll
    for (int t = 0; t < EK; t++) buf[t] = ~0ull;
    for (int r = 0; r < GRID; r++) {
        int s = 2 * r + 1;
        int ncub = s * s * s;
        for (int idx = lane; idx < ncub; idx += 32) {
            int dz = idx / (s * s) - r;
            int rem = idx % (s * s);
            int dy = rem / s - r;
            int dx = rem % s - r;
            int ch = abs(dx); if (abs(dy) > ch) ch = abs(dy); if (abs(dz) > ch) ch = abs(dz);
            if (ch != r) continue;   // shell only
            int ax = cx + dx, ay = cy + dy, az = cz + dz;
            if (ax < 0 || ax >= GRID || ay < 0 || ay >= GRID || az < 0 || az >= GRID) continue;
            int cell = ax + GRID * (ay + GRID * az);
            int st = g_cstart[cell];
            int cn = g_ccnt[cell];
            for (int p = 0; p < cn; p++) {
                int j = g_cpts[st + p];
                if (j == i) continue;
                float4 pj = g_sp4[j];
                float dot = fmaf(pi.z, pj.z, fmaf(pi.y, pj.y, __fmul_rn(pi.x, pj.x)));
                float d2 = __fsub_rn(__fadd_rn(pi.w, pj.w), __fmul_rn(2.0f, dot));
                unsigned long long key =
                    ((unsigned long long)f32_sortable(d2) << 32) | (unsigned int)j;
                if (key < buf[EK - 1]) {
                    buf[EK - 1] = key;
#pragma unroll
                    for (int t2 = EK - 1; t2 > 0; t2--) {
                        if (buf[t2] < buf[t2 - 1]) {
                            unsigned long long tmp = buf[t2]; buf[t2] = buf[t2 - 1]; buf[t2 - 1] = tmp;
                        }
                    }
                }
            }
        }
        __syncwarp();
        if (r >= 2) {
            // stop if >=15 found keys have d2 strictly below (r*h)^2 - slack
            float bound = (float)(r * r) * (1.0f / (GRID * GRID)) - 1e-5f;
            unsigned long long B = ((unsigned long long)f32_sortable(bound) << 32);
            int c = 0;
#pragma unroll
            for (int t = 0; t < EK; t++) c += (buf[t] < B);
#pragma unroll
            for (int o = 16; o > 0; o >>= 1) c += __shfl_xor_sync(0xffffffffu, c, o);
            if (c >= EK) break;
        }
    }
    // warp merge: 15 rounds of pop-min over per-lane sorted buffers
#pragma unroll 1
    for (int r = 0; r < EK; r++) {
        unsigned long long key = buf[0];
        unsigned long long kk = key;
#pragma unroll
        for (int o = 16; o > 0; o >>= 1) {
            unsigned long long o2 = __shfl_xor_sync(0xffffffffu, kk, o);
            if (o2 < kk) kk = o2;
        }
        if (lane == 0) g_nbr[i * EK + r] = (int)(kk & 0xFFFFFFFFull);
        if (key == kk) {
#pragma unroll
            for (int q = 0; q < EK - 1; q++) buf[q] = buf[q + 1];
            buf[EK - 1] = ~0ull;
        }
    }
}

// ---------------- 5. edge probs -> scatter into per-row buckets ----------------
__global__ void k_edges(const float* __restrict__ w_e) {
    __shared__ float swe[D];
    if (threadIdx.x < D) swe[threadIdx.x] = w_e[threadIdx.x];
    __syncthreads();
    int e = blockIdx.x * blockDim.x + threadIdx.x;
    if (e >= NS * EK) return;
    int i = e / EK;
    int j = g_nbr[e];
    const float* a = g_sx + i * D;
    const float* b = g_sx + j * D;
    float acc = 0.0f;
#pragma unroll 8
    for (int d = 0; d < D; d++)
        acc = fmaf(__fmul_rn(a[d], b[d]), swe[d], acc);   // bitwise symmetric in (i,j)
    float ep = sigmoid_exact(acc);
    int p1 = atomicAdd(&g_cnt[i], 1);
    if (p1 < MAXD) { g_scol[i * MAXD + p1] = j; g_sval[i * MAXD + p1] = ep; }
    int p2 = atomicAdd(&g_cnt[j], 1);
    if (p2 < MAXD) { g_scol[j * MAXD + p2] = i; g_sval[j * MAXD + p2] = ep; }
}

// ---------------- 6. per-row: sort by j, dedup, norm, deg (warp/row) ----------------
__global__ void k_rowsort() {
    __shared__ int   sj[4][MAXD];
    __shared__ float sv[4][MAXD];
    int gw   = (blockIdx.x * blockDim.x + threadIdx.x) >> 5;
    int wloc = (threadIdx.x >> 5);
    int lane = threadIdx.x & 31;
    if (gw >= NS) return;
    int n = min(g_cnt[gw], MAXD);
    int*   mj = sj[wloc];
    float* mv = sv[wloc];
    for (int t = lane; t < n; t += 32) { mj[t] = g_scol[gw * MAXD + t]; mv[t] = g_sval[gw * MAXD + t]; }
    __syncwarp();
    int   jr[8]; float vr[8]; int rr[8]; int ne = 0;
    for (int t = lane; t < n; t += 32) {
        int jt = mj[t]; float vt = mv[t];
        int r = 0;
        for (int m = 0; m < n; m++) {
            int jm = mj[m];
            r += (jm < jt) || (jm == jt && m < t);
        }
        jr[ne] = jt; vr[ne] = vt; rr[ne] = r; ne++;
    }
    __syncwarp();
    for (int q = 0; q < ne; q++) { mj[rr[q]] = jr[q]; mv[rr[q]] = vr[q]; }
    __syncwarp();
    if (lane == 0) {
        int cnt = 0, prev = -1;
        float s = 0.0f;
        for (int t = 0; t < n; t++) {
            int jt = mj[t];
            if (jt != prev) {
                float vt = mv[t];
                g_scol[gw * MAXD + cnt] = jt;
                g_sval[gw * MAXD + cnt] = vt;
                s = __fadd_rn(s, __fmul_rn(vt, vt));   // ascending-j chain
                cnt++; prev = jt;
            }
        }
        g_deg[gw] = cnt;
        g_norm[gw] = s;
    }
}

// ---------------- 7. fd2 top-16 via deterministic scatter SpGEMM (1 block/row) ----------------
__global__ void k_fd2() {
    __shared__ float sdot[NS];          // 16 KB
    __shared__ int   scol[MAXD];
    __shared__ float sval[MAXD];
    __shared__ unsigned long long swin[4];
    int i = blockIdx.x, tid = threadIdx.x;       // 128 threads
    int dg = g_deg[i];
    for (int t = tid; t < NS; t += 128) sdot[t] = 0.0f;
    for (int t = tid; t < dg; t += 128) { scol[t] = g_scol[i * MAXD + t]; sval[t] = g_sval[i * MAXD + t]; }
    __syncthreads();
    int jn0 = 0, jn1 = 0; float vn0 = 0.f, vn1 = 0.f; int dk_cur = 0;
    if (dg > 0) {
        int k = scol[0];
        dk_cur = g_deg[k];
        const int* ck = g_scol + k * MAXD; const float* cv = g_sval + k * MAXD;
        if (tid < dk_cur)        { jn0 = ck[tid];        vn0 = cv[tid]; }
        if (tid + 128 < dk_cur)  { jn1 = ck[tid + 128];  vn1 = cv[tid + 128]; }
    }
    for (int u = 0; u < dg; u++) {
        float aik = sval[u];
        int j20 = 0, j21 = 0; float v20 = 0.f, v21 = 0.f; int dk_next = 0;
        if (u + 1 < dg) {
            int k2 = scol[u + 1];
            dk_next = g_deg[k2];
            const int* ck = g_scol + k2 * MAXD; const float* cv = g_sval + k2 * MAXD;
            if (tid < dk_next)       { j20 = ck[tid];       v20 = cv[tid]; }
            if (tid + 128 < dk_next) { j21 = ck[tid + 128]; v21 = cv[tid + 128]; }
        }
        if (tid < dk_cur)       sdot[jn0] = fmaf(aik, vn0, sdot[jn0]);
        if (tid + 128 < dk_cur) sdot[jn1] = fmaf(aik, vn1, sdot[jn1]);
        __syncthreads();
        dk_cur = dk_next; jn0 = j20; vn0 = v20; jn1 = j21; vn1 = v21;
    }
    float ni = g_norm[i];
    float bd[KNN]; int bj[KNN];
#pragma unroll
    for (int t = 0; t < KNN; t++) { bd[t] = INFINITY; bj[t] = 0x7FFFFFFF; }
    for (int j = tid; j < NS; j += 128) {
        if (j == i) continue;
        float fd2 = __fsub_rn(__fadd_rn(ni, g_norm[j]), __fmul_rn(2.0f, sdot[j]));
        if (fd2 < bd[KNN - 1]) {
            bd[KNN - 1] = fd2; bj[KNN - 1] = j;
#pragma unroll
            for (int t2 = KNN - 1; t2 > 0; t2--) {
                if (bd[t2] < bd[t2 - 1]) {
                    float a = bd[t2]; bd[t2] = bd[t2 - 1]; bd[t2 - 1] = a;
                    int   b = bj[t2]; bj[t2] = bj[t2 - 1]; bj[t2 - 1] = b;
                }
            }
        }
    }
    __syncthreads();
    int wid = tid >> 5, lane = tid & 31;
#pragma unroll 1
    for (int r = 0; r < KNN; r++) {
        unsigned long long key =
            ((unsigned long long)f32_sortable(bd[0]) << 32) | (unsigned int)bj[0];
        unsigned long long kk = key;
#pragma unroll
        for (int o = 16; o > 0; o >>= 1) {
            unsigned long long o2 = __shfl_xor_sync(0xffffffffu, kk, o);
            if (o2 < kk) kk = o2;
        }
        if (lane == 0) swin[wid] = kk;
        __syncthreads();
        unsigned long long w = swin[0];
#pragma unroll
        for (int q = 1; q < 4; q++) if (swin[q] < w) w = swin[q];
        if (tid == 0) g_knn[i * KNN + r] = (int)(w & 0xFFFFFFFFull);
        if (key == w) {
#pragma unroll
            for (int q = 0; q < KNN - 1; q++) { bd[q] = bd[q + 1]; bj[q] = bj[q + 1]; }
            bd[KNN - 1] = INFINITY; bj[KNN - 1] = 0x7FFFFFFF;
        }
        __syncthreads();
    }
}

// ---------------- 8. per-vertex MLP projection p_v = [sx_v, sp_v] @ Wf1 ----------------
__global__ void k_pfeat(const float* __restrict__ Wf1) {
    __shared__ float sW[(D + 3) * H];
    int tid = threadIdx.x;
    for (int t = tid; t < (D + 3) * H; t += blockDim.x) sW[t] = Wf1[t];
    __syncthreads();
    int warp = (blockIdx.x * blockDim.x + tid) >> 5;
    int lane = tid & 31;
    if (warp >= NS) return;
    float acc[4] = {0.f, 0.f, 0.f, 0.f};
#pragma unroll 8
    for (int d = 0; d < D; d++) {
        float xv = g_sx[warp * D + d];
#pragma unroll
        for (int q = 0; q < 4; q++) acc[q] = fmaf(xv, sW[d * H + lane + q * 32], acc[q]);
    }
#pragma unroll
    for (int c = 0; c < 3; c++) {
        float pv = g_sp[warp * 3 + c];
#pragma unroll
        for (int q = 0; q < 4; q++) acc[q] = fmaf(pv, sW[(D + c) * H + lane + q * 32], acc[q]);
    }
#pragma unroll
    for (int q = 0; q < 4; q++) g_p[warp * H + lane + q * 32] = acc[q];
}

// ---------------- 9. triangles: fprob/tprob (1 block/row, thread/pair) ----------------
__global__ void k_tri(const float* __restrict__ bf1, const float* __restrict__ wf2,
                      float* __restrict__ out) {
    __shared__ float spn[KNN * 132];
    __shared__ float spi[H];
    __shared__ float sb[H];
    __shared__ float sw[H];
    __shared__ int   sknn[KNN];
    __shared__ float sain[KNN];
    int i = blockIdx.x, tid = threadIdx.x;
    if (tid < KNN) sknn[tid] = g_knn[i * KNN + tid];
    if (tid < H) { spi[tid] = g_p[i * H + tid]; sb[tid] = bf1[tid]; sw[tid] = wf2[tid]; }
    __syncthreads();
    for (int t = tid; t < KNN * H; t += 128) {
        int r = t >> 7, h = t & 127;
        spn[r * 132 + h] = g_p[sknn[r] * H + h];
    }
    if (tid < KNN) sain[tid] = adj_lookup(i, sknn[tid]);
    __syncthreads();
    if (tid < NPAIR) {
        int rem = tid, jj = 0;
        while (rem >= EK - jj) { rem -= EK - jj; jj++; }
        int ll = jj + 1 + rem;
        int n1 = sknn[jj], n2 = sknn[ll];
        float a12 = adj_lookup(n1, n2);
        const float* p1 = spn + jj * 132;
        const float* p2 = spn + ll * 132;
        float acc = 0.0f;
#pragma unroll 8
        for (int h = 0; h < H; h++) {
            float pre = __fadd_rn(__fdiv_rn(__fadd_rn(__fadd_rn(spi[h], p1[h]), p2[h]), 3.0f),
                                  sb[h]);
            acc = fmaf(fmaxf(pre, 0.0f), sw[h], acc);
        }
        float valid = (a12 > 0.0f) ? 1.0f : 0.0f;
        float fp = sigmoid_fast(acc) * valid;
        float prod = __fmul_rn(__fmul_rn(sain[jj], sain[ll]), a12);
        float tp = (a12 > 0.0f) ? cbrtf(fmaxf(prod, 1e-9f)) : 0.0f;
        out[(size_t)i * NPAIR + tid]                      = fp;
        out[(size_t)NS * NPAIR + (size_t)i * NPAIR + tid] = tp;
    }
}

// ---------------- launch ----------------
extern "C" void kernel_launch(void* const* d_in, const int* in_sizes, int n_in,
                              void* d_out, int out_size) {
    const float* x   = (const float*)d_in[0];
    const float* pos = (const float*)d_in[1];
    const float* W1  = (const float*)d_in[2];
    const float* b1  = (const float*)d_in[3];
    const float* w2  = (const float*)d_in[4];
    const float* w_e = (const float*)d_in[5];
    const float* Wf1 = (const float*)d_in[6];
    const float* bf1 = (const float*)d_in[7];
    const float* wf2 = (const float*)d_in[8];
    float* out = (float*)d_out;

    k_logits<<<(N_IN * 32 + 255) / 256, 256>>>(x, W1, b1, w2);
    k_rank<<<(N_IN + 255) / 256, 256>>>();
    k_gather<<<(NS * D + 255) / 256, 256>>>(x, pos);
    k_cscan<<<1, 1024>>>();
    k_cscatter<<<(NS + 255) / 256, 256>>>();
    k_knn_space<<<(NS * 32 + 255) / 256, 256>>>();
    k_edges<<<(NS * EK + 255) / 256, 256>>>(w_e);
    k_rowsort<<<(NS * 32 + 127) / 128, 128>>>();
    k_fd2<<<NS, 128>>>();
    k_pfeat<<<(NS * 32 + 255) / 256, 256>>>(Wf1);
    k_tri<<<NS, 128>>>(bf1, wf2, out);
}

// round 9
// speedup vs baseline: 3.1587x; 1.2281x over previous
#include <cuda_runtime.h>
#include <math.h>

#define N_IN  8000
#define NS    4000
#define D     64
#define H     128
#define EK    15
#define KNN   16
#define NPAIR 120
#define MAXD  256
#define GRID  16
#define NCELL (GRID * GRID * GRID)
#define RCH   8
#define RCHN  (N_IN / RCH)   // 1000

// ---------------- scratch (no allocations allowed) ----------------
__device__ float g_prob[N_IN];
__device__ int   g_rank[N_IN];
__device__ int   g_sel[NS];
__device__ int   g_cnt[NS];
__device__ float g_sx[NS * D];
__device__ float g_sp[NS * 3];
__device__ float4 g_sp4[NS];
__device__ int   g_nbr[NS * EK];
__device__ int   g_deg[NS];
__device__ int   g_scol[NS * MAXD];    // unsorted buckets, then sorted CSR (in place)
__device__ float g_sval[NS * MAXD];
__device__ float g_norm[NS];
__device__ int   g_knn[NS * KNN];
__device__ float g_p[NS * H];
// spatial grid
__device__ int   g_ccnt[NCELL];
__device__ int   g_cstart[NCELL];
__device__ int   g_pcell[NS];
__device__ int   g_pslot[NS];
__device__ int   g_cpts[NS];

__device__ __forceinline__ float sigmoid_fast(float v) { return 1.0f / (1.0f + expf(-v)); }
// near-correctly-rounded fp32 sigmoid — matches libm expf bits
__device__ __forceinline__ float sigmoid_exact(float v) {
    float e = (float)exp(-(double)v);
    return __fdiv_rn(1.0f, __fadd_rn(1.0f, e));
}
__device__ __forceinline__ unsigned int f32_sortable(float f) {
    unsigned int b = __float_as_uint(f);
    return (b & 0x80000000u) ? ~b : (b | 0x80000000u);
}
// sorted-CSR point lookup (rows ascending in j)
__device__ __forceinline__ float adj_lookup(int r, int j) {
    const int* c = g_scol + r * MAXD;
    int n = g_deg[r];
    int lo = 0, hi = n;
    while (lo < hi) { int mid = (lo + hi) >> 1; if (c[mid] < j) lo = mid + 1; else hi = mid; }
    return (lo < n && c[lo] == j) ? g_sval[r * MAXD + lo] : 0.0f;
}

// ---------------- 1. probs = sigmoid(relu(x@W1 + b1) @ w2), Eigen bit-model ----------------
// Prologue also zeroes the counters consumed by later kernels (stream-ordered).
__global__ void k_logits(const float* __restrict__ x, const float* __restrict__ W1,
                         const float* __restrict__ b1, const float* __restrict__ w2) {
    __shared__ float sW[D * H];
    __shared__ float sw2[H];
    __shared__ float sb1[H];
    __shared__ float sh[8][H];
    int tid = threadIdx.x;
    int gt = blockIdx.x * blockDim.x + tid;
    if (gt < N_IN) g_rank[gt] = 0;
    if (gt < NS)   g_cnt[gt] = 0;
    if (gt < NCELL) g_ccnt[gt] = 0;
    for (int t = tid; t < D * H; t += blockDim.x) sW[t] = W1[t];
    if (tid < H) { sw2[tid] = w2[tid]; sb1[tid] = b1[tid]; }
    __syncthreads();
    int warp = gt >> 5;
    int wloc = (tid >> 5);
    int lane = tid & 31;
    if (warp >= N_IN) return;
    const float* xr = x + warp * D;
    float acc[4] = {0.f, 0.f, 0.f, 0.f};
#pragma unroll 8
    for (int d = 0; d < D; d++) {
        float xv = xr[d];
#pragma unroll
        for (int q = 0; q < 4; q++) acc[q] = fmaf(xv, sW[d * H + lane + q * 32], acc[q]);
    }
#pragma unroll
    for (int q = 0; q < 4; q++) {
        int j = lane + q * 32;
        sh[wloc][j] = fmaxf(__fadd_rn(acc[q], sb1[j]), 0.0f);
    }
    __syncwarp();
    if (lane == 0) {
        float logit = 0.0f;
#pragma unroll 8
        for (int j = 0; j < H; j++) logit = fmaf(sh[wloc][j], sw2[j], logit);
        g_prob[warp] = sigmoid_exact(logit);
    }
}

// ---------------- 2a. partial ranks over j-chunks (desc prob, asc-index ties) ----------------
__global__ void k_rank1() {
    __shared__ float sp[RCHN];      // 4 KB
    int tid = threadIdx.x;
    int jc = blockIdx.x & (RCH - 1);
    int ib = blockIdx.x >> 3;
    int jbase = jc * RCHN;
    for (int t = tid; t < RCHN; t += blockDim.x) sp[t] = g_prob[jbase + t];
    __syncthreads();
    int i = ib * 256 + tid;
    if (i >= N_IN) return;
    float pi = g_prob[i];
    int r = 0;
#pragma unroll 8
    for (int j = 0; j < RCHN; j++) {
        float pj = sp[j];
        r += (pj > pi) || (pj == pi && (jbase + j) < i);
    }
    atomicAdd(&g_rank[i], r);
}
// ---------------- 2b. scatter: sel[rank] = i ----------------
__global__ void k_rank2() {
    int i = blockIdx.x * blockDim.x + threadIdx.x;
    if (i >= N_IN) return;
    int r = g_rank[i];
    if (r < NS) g_sel[r] = i;
}

// ---------------- 3. gather sx/sp, pack (x,y,z,|p|^2), grid-cell insert ----------------
__global__ void k_gather(const float* __restrict__ x, const float* __restrict__ pos) {
    int t = blockIdx.x * blockDim.x + threadIdx.x;
    if (t < NS * D) {
        int r = t >> 6, d = t & 63;
        g_sx[t] = x[g_sel[r] * D + d];
    }
    if (t < NS * 3) {
        int r = t / 3, c = t % 3;
        g_sp[t] = pos[g_sel[r] * 3 + c];
    }
    if (t < NS) {
        int sI = g_sel[t];
        float a = pos[sI * 3], b = pos[sI * 3 + 1], c = pos[sI * 3 + 2];
        float sq = __fadd_rn(__fadd_rn(__fmul_rn(a, a), __fmul_rn(b, b)), __fmul_rn(c, c));
        g_sp4[t] = make_float4(a, b, c, sq);
        int ix = min(GRID - 1, max(0, (int)(a * GRID)));
        int iy = min(GRID - 1, max(0, (int)(b * GRID)));
        int iz = min(GRID - 1, max(0, (int)(c * GRID)));
        int cell = ix + GRID * (iy + GRID * iz);
        g_pcell[t] = cell;
        g_pslot[t] = atomicAdd(&g_ccnt[cell], 1);
    }
}

// ---------------- 3b. warp-shfl exclusive scan over 4096 cells + point scatter ----------------
__global__ void k_cscan() {
    __shared__ int warpsum[32];
    int tid = threadIdx.x;          // 1024
    int lane = tid & 31, wid = tid >> 5;
    int base = tid * 4;
    int v0 = g_ccnt[base], v1 = g_ccnt[base + 1], v2 = g_ccnt[base + 2], v3 = g_ccnt[base + 3];
    int s = v0 + v1 + v2 + v3;
    int sc = s;
#pragma unroll
    for (int o = 1; o < 32; o <<= 1) {
        int n = __shfl_up_sync(0xffffffffu, sc, o);
        if (lane >= o) sc += n;
    }
    if (lane == 31) warpsum[wid] = sc;
    __syncthreads();
    if (wid == 0) {
        int ws = warpsum[lane];
        int wsc = ws;
#pragma unroll
        for (int o = 1; o < 32; o <<= 1) {
            int n = __shfl_up_sync(0xffffffffu, wsc, o);
            if (lane >= o) wsc += n;
        }
        warpsum[lane] = wsc;
    }
    __syncthreads();
    int off = (wid > 0 ? warpsum[wid - 1] : 0) + (sc - s);
    g_cstart[base] = off;
    g_cstart[base + 1] = off + v0;
    g_cstart[base + 2] = off + v0 + v1;
    g_cstart[base + 3] = off + v0 + v1 + v2;
    __syncthreads();
    for (int t = tid; t < NS; t += 1024)
        g_cpts[g_cstart[g_pcell[t]] + g_pslot[t]] = t;
}

// ---------------- 4. grid-accelerated exact 15-NN, warp per i ----------------
__global__ void k_knn_space() {
    int i = (blockIdx.x * blockDim.x + threadIdx.x) >> 5;
    int lane = threadIdx.x & 31;
    if (i >= NS) return;
    float4 pi = g_sp4[i];
    int cx = min(GRID - 1, max(0, (int)(pi.x * GRID)));
    int cy = min(GRID - 1, max(0, (int)(pi.y * GRID)));
    int cz = min(GRID - 1, max(0, (int)(pi.z * GRID)));
    unsigned long long buf[EK];
#pragma unroll
    for (int t = 0; t < EK; t++) buf[t] = ~0ull;
    for (int r = 0; r < GRID; r++) {
        int s = 2 * r + 1;
        int ncub = s * s * s;
        for (int idx = lane; idx < ncub; idx += 32) {
            int dz = idx / (s * s) - r;
            int rem = idx % (s * s);
            int dy = rem / s - r;
            int dx = rem % s - r;
            int ch = abs(dx); if (abs(dy) > ch) ch = abs(dy); if (abs(dz) > ch) ch = abs(dz);
            if (ch != r) continue;   // shell only
            int ax = cx + dx, ay = cy + dy, az = cz + dz;
            if (ax < 0 || ax >= GRID || ay < 0 || ay >= GRID || az < 0 || az >= GRID) continue;
            int cell = ax + GRID * (ay + GRID * az);
            int st = g_cstart[cell];
            int cn = g_ccnt[cell];
            for (int p = 0; p < cn; p++) {
                int j = g_cpts[st + p];
                if (j == i) continue;
                float4 pj = g_sp4[j];
                float dot = fmaf(pi.z, pj.z, fmaf(pi.y, pj.y, __fmul_rn(pi.x, pj.x)));
                float d2 = __fsub_rn(__fadd_rn(pi.w, pj.w), __fmul_rn(2.0f, dot));
                unsigned long long key =
                    ((unsigned long long)f32_sortable(d2) << 32) | (unsigned int)j;
                if (key < buf[EK - 1]) {
                    buf[EK - 1] = key;
#pragma unroll
                    for (int t2 = EK - 1; t2 > 0; t2--) {
                        if (buf[t2] < buf[t2 - 1]) {
                            unsigned long long tmp = buf[t2]; buf[t2] = buf[t2 - 1]; buf[t2 - 1] = tmp;
                        }
                    }
                }
            }
        }
        __syncwarp();
        if (r >= 2) {
            float bound = (float)(r * r) * (1.0f / (GRID * GRID)) - 1e-5f;
            unsigned long long B = ((unsigned long long)f32_sortable(bound) << 32);
            int c = 0;
#pragma unroll
            for (int t = 0; t < EK; t++) c += (buf[t] < B);
#pragma unroll
            for (int o = 16; o > 0; o >>= 1) c += __shfl_xor_sync(0xffffffffu, c, o);
            if (c >= EK) break;
        }
    }
#pragma unroll 1
    for (int r = 0; r < EK; r++) {
        unsigned long long key = buf[0];
        unsigned long long kk = key;
#pragma unroll
        for (int o = 16; o > 0; o >>= 1) {
            unsigned long long o2 = __shfl_xor_sync(0xffffffffu, kk, o);
            if (o2 < kk) kk = o2;
        }
        if (lane == 0) g_nbr[i * EK + r] = (int)(kk & 0xFFFFFFFFull);
        if (key == kk) {
#pragma unroll
            for (int q = 0; q < EK - 1; q++) buf[q] = buf[q + 1];
            buf[EK - 1] = ~0ull;
        }
    }
}

// ---------------- 5. edge probs -> scatter into per-row buckets ----------------
__global__ void k_edges(const float* __restrict__ w_e) {
    __shared__ float swe[D];
    if (threadIdx.x < D) swe[threadIdx.x] = w_e[threadIdx.x];
    __syncthreads();
    int e = blockIdx.x * blockDim.x + threadIdx.x;
    if (e >= NS * EK) return;
    int i = e / EK;
    int j = g_nbr[e];
    const float* a = g_sx + i * D;
    const float* b = g_sx + j * D;
    float acc = 0.0f;
#pragma unroll 8
    for (int d = 0; d < D; d++)
        acc = fmaf(__fmul_rn(a[d], b[d]), swe[d], acc);   // bitwise symmetric in (i,j)
    float ep = sigmoid_exact(acc);
    int p1 = atomicAdd(&g_cnt[i], 1);
    if (p1 < MAXD) { g_scol[i * MAXD + p1] = j; g_sval[i * MAXD + p1] = ep; }
    int p2 = atomicAdd(&g_cnt[j], 1);
    if (p2 < MAXD) { g_scol[j * MAXD + p2] = i; g_sval[j * MAXD + p2] = ep; }
}

// ---------------- 6. per-row: sort by j, dedup, norm, deg (warp/row) ----------------
__global__ void k_rowsort() {
    __shared__ int   sj[4][MAXD];
    __shared__ float sv[4][MAXD];
    int gw   = (blockIdx.x * blockDim.x + threadIdx.x) >> 5;
    int wloc = (threadIdx.x >> 5);
    int lane = threadIdx.x & 31;
    if (gw >= NS) return;
    int n = min(g_cnt[gw], MAXD);
    int*   mj = sj[wloc];
    float* mv = sv[wloc];
    for (int t = lane; t < n; t += 32) { mj[t] = g_scol[gw * MAXD + t]; mv[t] = g_sval[gw * MAXD + t]; }
    __syncwarp();
    int   jr[8]; float vr[8]; int rr[8]; int ne = 0;
    for (int t = lane; t < n; t += 32) {
        int jt = mj[t]; float vt = mv[t];
        int r = 0;
        for (int m = 0; m < n; m++) {
            int jm = mj[m];
            r += (jm < jt) || (jm == jt && m < t);
        }
        jr[ne] = jt; vr[ne] = vt; rr[ne] = r; ne++;
    }
    __syncwarp();
    for (int q = 0; q < ne; q++) { mj[rr[q]] = jr[q]; mv[rr[q]] = vr[q]; }
    __syncwarp();
    if (lane == 0) {
        int cnt = 0, prev = -1;
        float s = 0.0f;
        for (int t = 0; t < n; t++) {
            int jt = mj[t];
            if (jt != prev) {
                float vt = mv[t];
                g_scol[gw * MAXD + cnt] = jt;
                g_sval[gw * MAXD + cnt] = vt;
                s = __fadd_rn(s, __fmul_rn(vt, vt));   // ascending-j chain
                cnt++; prev = jt;
            }
        }
        g_deg[gw] = cnt;
        g_norm[gw] = s;
    }
}

// ---------------- 7. fd2 top-16 via deterministic scatter SpGEMM (1 block/row) ----------------
__global__ void k_fd2() {
    __shared__ float sdot[NS];          // 16 KB
    __shared__ int   scol[MAXD];
    __shared__ float sval[MAXD];
    __shared__ unsigned long long swin[4];
    int i = blockIdx.x, tid = threadIdx.x;       // 128 threads
    int dg = g_deg[i];
    for (int t = tid; t < NS; t += 128) sdot[t] = 0.0f;
    for (int t = tid; t < dg; t += 128) { scol[t] = g_scol[i * MAXD + t]; sval[t] = g_sval[i * MAXD + t]; }
    __syncthreads();
    int jn0 = 0, jn1 = 0; float vn0 = 0.f, vn1 = 0.f; int dk_cur = 0;
    if (dg > 0) {
        int k = scol[0];
        dk_cur = g_deg[k];
        const int* ck = g_scol + k * MAXD; const float* cv = g_sval + k * MAXD;
        if (tid < dk_cur)        { jn0 = ck[tid];        vn0 = cv[tid]; }
        if (tid + 128 < dk_cur)  { jn1 = ck[tid + 128];  vn1 = cv[tid + 128]; }
    }
    for (int u = 0; u < dg; u++) {
        float aik = sval[u];
        int j20 = 0, j21 = 0; float v20 = 0.f, v21 = 0.f; int dk_next = 0;
        if (u + 1 < dg) {
            int k2 = scol[u + 1];
            dk_next = g_deg[k2];
            const int* ck = g_scol + k2 * MAXD; const float* cv = g_sval + k2 * MAXD;
            if (tid < dk_next)       { j20 = ck[tid];       v20 = cv[tid]; }
            if (tid + 128 < dk_next) { j21 = ck[tid + 128]; v21 = cv[tid + 128]; }
        }
        if (tid < dk_cur)       sdot[jn0] = fmaf(aik, vn0, sdot[jn0]);
        if (tid + 128 < dk_cur) sdot[jn1] = fmaf(aik, vn1, sdot[jn1]);
        __syncthreads();
        dk_cur = dk_next; jn0 = j20; vn0 = v20; jn1 = j21; vn1 = v21;
    }
    float ni = g_norm[i];
    float bd[KNN]; int bj[KNN];
#pragma unroll
    for (int t = 0; t < KNN; t++) { bd[t] = INFINITY; bj[t] = 0x7FFFFFFF; }
    for (int j = tid; j < NS; j += 128) {
        if (j == i) continue;
        float fd2 = __fsub_rn(__fadd_rn(ni, g_norm[j]), __fmul_rn(2.0f, sdot[j]));
        if (fd2 < bd[KNN - 1]) {
            bd[KNN - 1] = fd2; bj[KNN - 1] = j;
#pragma unroll
            for (int t2 = KNN - 1; t2 > 0; t2--) {
                if (bd[t2] < bd[t2 - 1]) {
                    float a = bd[t2]; bd[t2] = bd[t2 - 1]; bd[t2 - 1] = a;
                    int   b = bj[t2]; bj[t2] = bj[t2 - 1]; bj[t2 - 1] = b;
                }
            }
        }
    }
    __syncthreads();
    int wid = tid >> 5, lane = tid & 31;
#pragma unroll 1
    for (int r = 0; r < KNN; r++) {
        unsigned long long key =
            ((unsigned long long)f32_sortable(bd[0]) << 32) | (unsigned int)bj[0];
        unsigned long long kk = key;
#pragma unroll
        for (int o = 16; o > 0; o >>= 1) {
            unsigned long long o2 = __shfl_xor_sync(0xffffffffu, kk, o);
            if (o2 < kk) kk = o2;
        }
        if (lane == 0) swin[wid] = kk;
        __syncthreads();
        unsigned long long w = swin[0];
#pragma unroll
        for (int q = 1; q < 4; q++) if (swin[q] < w) w = swin[q];
        if (tid == 0) g_knn[i * KNN + r] = (int)(w & 0xFFFFFFFFull);
        if (key == w) {
#pragma unroll
            for (int q = 0; q < KNN - 1; q++) { bd[q] = bd[q + 1]; bj[q] = bj[q + 1]; }
            bd[KNN - 1] = INFINITY; bj[KNN - 1] = 0x7FFFFFFF;
        }
        __syncthreads();
    }
}

// ---------------- 8. per-vertex MLP projection p_v = [sx_v, sp_v] @ Wf1 ----------------
__global__ void k_pfeat(const float* __restrict__ Wf1) {
    __shared__ float sW[(D + 3) * H];
    int tid = threadIdx.x;
    for (int t = tid; t < (D + 3) * H; t += blockDim.x) sW[t] = Wf1[t];
    __syncthreads();
    int warp = (blockIdx.x * blockDim.x + tid) >> 5;
    int lane = tid & 31;
    if (warp >= NS) return;
    float acc[4] = {0.f, 0.f, 0.f, 0.f};
#pragma unroll 8
    for (int d = 0; d < D; d++) {
        float xv = g_sx[warp * D + d];
#pragma unroll
        for (int q = 0; q < 4; q++) acc[q] = fmaf(xv, sW[d * H + lane + q * 32], acc[q]);
    }
#pragma unroll
    for (int c = 0; c < 3; c++) {
        float pv = g_sp[warp * 3 + c];
#pragma unroll
        for (int q = 0; q < 4; q++) acc[q] = fmaf(pv, sW[(D + c) * H + lane + q * 32], acc[q]);
    }
#pragma unroll
    for (int q = 0; q < 4; q++) g_p[warp * H + lane + q * 32] = acc[q];
}

// ---------------- 9. triangles: fprob/tprob (1 block/row, thread/pair) ----------------
__global__ void k_tri(const float* __restrict__ bf1, const float* __restrict__ wf2,
                      float* __restrict__ out) {
    __shared__ float spn[KNN * 132];
    __shared__ float spi[H];
    __shared__ float sb[H];
    __shared__ float sw[H];
    __shared__ int   sknn[KNN];
    __shared__ float sain[KNN];
    int i = blockIdx.x, tid = threadIdx.x;
    if (tid < KNN) sknn[tid] = g_knn[i * KNN + tid];
    if (tid < H) { spi[tid] = g_p[i * H + tid]; sb[tid] = bf1[tid]; sw[tid] = wf2[tid]; }
    __syncthreads();
    for (int t = tid; t < KNN * H; t += 128) {
        int r = t >> 7, h = t & 127;
        spn[r * 132 + h] = g_p[sknn[r] * H + h];
    }
    if (tid < KNN) sain[tid] = adj_lookup(i, sknn[tid]);
    __syncthreads();
    if (tid < NPAIR) {
        int rem = tid, jj = 0;
        while (rem >= EK - jj) { rem -= EK - jj; jj++; }
        int ll = jj + 1 + rem;
        int n1 = sknn[jj], n2 = sknn[ll];
        float a12 = adj_lookup(n1, n2);
        const float* p1 = spn + jj * 132;
        const float* p2 = spn + ll * 132;
        float acc = 0.0f;
        const float third = 0.3333333333333333f;
#pragma unroll 8
        for (int h = 0; h < H; h++) {
            // continuous-output path: (sum*1/3 + b) vs (sum/3 + b) differs ~1ulp, OK
            float pre = fmaf(__fadd_rn(__fadd_rn(spi[h], p1[h]), p2[h]), third, sb[h]);
            acc = fmaf(fmaxf(pre, 0.0f), sw[h], acc);
        }
        float valid = (a12 > 0.0f) ? 1.0f : 0.0f;
        float fp = sigmoid_fast(acc) * valid;
        float prod = __fmul_rn(__fmul_rn(sain[jj], sain[ll]), a12);
        float tp = (a12 > 0.0f) ? cbrtf(fmaxf(prod, 1e-9f)) : 0.0f;
        out[(size_t)i * NPAIR + tid]                      = fp;
        out[(size_t)NS * NPAIR + (size_t)i * NPAIR + tid] = tp;
    }
}

// ---------------- launch ----------------
extern "C" void kernel_launch(void* const* d_in, const int* in_sizes, int n_in,
                              void* d_out, int out_size) {
    const float* x   = (const float*)d_in[0];
    const float* pos = (const float*)d_in[1];
    const float* W1  = (const float*)d_in[2];
    const float* b1  = (const float*)d_in[3];
    const float* w2  = (const float*)d_in[4];
    const float* w_e = (const float*)d_in[5];
    const float* Wf1 = (const float*)d_in[6];
    const float* bf1 = (const float*)d_in[7];
    const float* wf2 = (const float*)d_in[8];
    float* out = (float*)d_out;

    k_logits<<<(N_IN * 32 + 255) / 256, 256>>>(x, W1, b1, w2);
    k_rank1<<<((N_IN + 255) / 256) * RCH, 256>>>();   // FIX: ceil-div (was 31*8, dropped i>=7936)
    k_rank2<<<(N_IN + 255) / 256, 256>>>();
    k_gather<<<(NS * D + 255) / 256, 256>>>(x, pos);
    k_cscan<<<1, 1024>>>();
    k_knn_space<<<(NS * 32 + 255) / 256, 256>>>();
    k_edges<<<(NS * EK + 255) / 256, 256>>>(w_e);
    k_rowsort<<<(NS * 32 + 127) / 128, 128>>>();
    k_fd2<<<NS, 128>>>();
    k_pfeat<<<(NS * 32 + 255) / 256, 256>>>(Wf1);
    k_tri<<<NS, 128>>>(bf1, wf2, out);
}